// round 2
// baseline (speedup 1.0000x reference)
#include <cuda_runtime.h>
#include <math.h>

#define T_STEPS 512
#define B_SZ    128
#define NI_SZ   512
#define D_SZ    512
#define G4_SZ   2048   // 4*D

typedef unsigned long long u64;

// Scratch for intern = X@Wf + bf
__device__ float g_intern[(size_t)T_STEPS * B_SZ * G4_SZ];

// packed fp32x2 FMA: d = a*b + d (lanewise on 2 packed floats)
__device__ __forceinline__ void ffma2(u64 &d, u64 a, u64 b) {
    asm("fma.rn.f32x2 %0, %1, %2, %0;" : "+l"(d) : "l"(a), "l"(b));
}

// ---------------------------------------------------------------------------
// Phase 1: intern[M=65536][2048] = X[M][512] @ Wf[512][2048] + bf
// (unchanged from R1 — ~12% of runtime)
// ---------------------------------------------------------------------------
__global__ __launch_bounds__(256)
void gemm_intern_kernel(const float* __restrict__ X,
                        const float* __restrict__ Wf,
                        const float* __restrict__ bf)
{
    __shared__ __align__(16) float As[8][128];
    __shared__ __align__(16) float Bs[8][128];

    const int t  = threadIdx.x;
    const int tx = t & 15;
    const int ty = t >> 4;
    const int m0 = blockIdx.y * 128;
    const int n0 = blockIdx.x * 128;

    const int arow = t >> 1, acol = (t & 1) * 4;
    const int brow = t >> 5, bcol = (t & 31) * 4;

    const float* Aptr = X  + (size_t)(m0 + arow) * NI_SZ + acol;
    const float* Bptr = Wf + (size_t)brow * G4_SZ + n0 + bcol;

    float acc[8][8];
    #pragma unroll
    for (int i = 0; i < 8; i++)
        #pragma unroll
        for (int j = 0; j < 8; j++) acc[i][j] = 0.f;

    for (int k0 = 0; k0 < NI_SZ; k0 += 8) {
        float4 av = *(const float4*)(Aptr + k0);
        float4 bv = *(const float4*)(Bptr + (size_t)k0 * G4_SZ);
        __syncthreads();
        As[acol + 0][arow] = av.x;
        As[acol + 1][arow] = av.y;
        As[acol + 2][arow] = av.z;
        As[acol + 3][arow] = av.w;
        *(float4*)&Bs[brow][bcol] = bv;
        __syncthreads();
        #pragma unroll
        for (int k = 0; k < 8; k++) {
            float a[8], b[8];
            *(float4*)(a)     = *(const float4*)&As[k][ty * 4];
            *(float4*)(a + 4) = *(const float4*)&As[k][64 + ty * 4];
            *(float4*)(b)     = *(const float4*)&Bs[k][tx * 4];
            *(float4*)(b + 4) = *(const float4*)&Bs[k][64 + tx * 4];
            #pragma unroll
            for (int i = 0; i < 8; i++)
                #pragma unroll
                for (int j = 0; j < 8; j++)
                    acc[i][j] = fmaf(a[i], b[j], acc[i][j]);
        }
    }

    float4 bias0 = *(const float4*)&bf[n0 + tx * 4];
    float4 bias1 = *(const float4*)&bf[n0 + 64 + tx * 4];
    #pragma unroll
    for (int i = 0; i < 8; i++) {
        int m = m0 + (i < 4 ? ty * 4 + i : 64 + ty * 4 + (i - 4));
        float* out = g_intern + (size_t)m * G4_SZ + n0;
        float4 v0 = make_float4(acc[i][0] + bias0.x, acc[i][1] + bias0.y,
                                acc[i][2] + bias0.z, acc[i][3] + bias0.w);
        float4 v1 = make_float4(acc[i][4] + bias1.x, acc[i][5] + bias1.y,
                                acc[i][6] + bias1.z, acc[i][7] + bias1.w);
        *(float4*)(out + tx * 4)      = v0;
        *(float4*)(out + 64 + tx * 4) = v1;
    }
}

// ---------------------------------------------------------------------------
// Phase 2: one LSTM step with packed fp32x2 FMA + register-prefetch pipeline.
// CTA tile: 32 b x 16 j (x4 gates). 256 threads = 4 k-splits x 64 slots.
// Slot: bg(0..7) -> 4 b's, jp(0..7) -> j-pair. Thread tile 4b x (2j x 4g)
// as 16 packed-f32x2 accumulators. h duplicated in smem, w in j-pairs.
// ---------------------------------------------------------------------------
#define KC    16
#define HROW  68          // 32 b * 2 (dup) + pad, 16B-aligned rows
#define WROW  72          // 8 jp * 8 (4 gates x j-pair) + pad
#define HSPL  (KC * HROW) // 1088 floats per split
#define WSPL  (KC * WROW) // 1152 floats per split

__global__ __launch_bounds__(256)
void lstm_step_kernel(int tstep,
                      const float* __restrict__ h_prev,
                      const float* __restrict__ c_prev,
                      const float* __restrict__ i_t,
                      const float* __restrict__ Wr,
                      float* __restrict__ Y_t,
                      float* __restrict__ C_t,
                      float* __restrict__ d_fin)
{
    __shared__ __align__(16) float smem[4 * HSPL + 4 * WSPL]; // 8960 floats = 35 KB
    float* Hs = smem;
    float* Ws = smem + 4 * HSPL;

    const float* intern_t = g_intern + (size_t)tstep * B_SZ * G4_SZ;

    const int t    = threadIdx.x;
    const int ks   = t >> 6;        // k-split (128 k each)
    const int slot = t & 63;
    const int bg   = slot >> 3;     // b-group of 4
    const int jp   = slot & 7;      // j-pair
    const int j0   = blockIdx.x * 16;
    const int bm0  = blockIdx.y * 32;

    // ---- staging index precompute (h: 2 float4/thread, w: 4 float4/thread)
    int h_soff[2];
    const float* h_gp[2];
    #pragma unroll
    for (int u = 0; u < 2; u++) {
        int idx = u * 256 + t;
        int ks2 = idx >> 7, r = idx & 127;
        int b = r >> 2, kq = r & 3;
        h_gp[u]   = h_prev + (size_t)(bm0 + b) * D_SZ + ks2 * 128 + kq * 4;
        h_soff[u] = ks2 * HSPL + (kq * 4) * HROW + b * 2;
    }
    int w_soff[4], w_jq[4];
    const float* w_gp[4];
    #pragma unroll
    for (int u = 0; u < 4; u++) {
        int idx = u * 256 + t;
        int ks2 = idx >> 8, r = idx & 255;
        int kk = r >> 4, g = (r >> 2) & 3, jq = r & 3;
        w_gp[u]   = Wr + (size_t)(ks2 * 128 + kk) * G4_SZ + g * D_SZ + j0 + jq * 4;
        w_soff[u] = ks2 * WSPL + kk * WROW + g * 2;
        w_jq[u]   = jq;
    }

    u64 acc[4][4];
    #pragma unroll
    for (int i = 0; i < 4; i++)
        #pragma unroll
        for (int g = 0; g < 4; g++) acc[i][g] = 0ull;

    // ---- preload chunk 0
    float4 hv[2], wv[4];
    #pragma unroll
    for (int u = 0; u < 2; u++) hv[u] = *(const float4*)(h_gp[u]);
    #pragma unroll
    for (int u = 0; u < 4; u++) wv[u] = *(const float4*)(w_gp[u]);

    const float* hb = Hs + ks * HSPL + bg * 8;
    const float* wb = Ws + ks * WSPL + jp * 8;

    for (int ci = 0; ci < 8; ci++) {
        __syncthreads();
        // ---- commit staged regs to smem
        #pragma unroll
        for (int u = 0; u < 2; u++) {
            float* dst = Hs + h_soff[u];
            *(float2*)(dst + 0 * HROW) = make_float2(hv[u].x, hv[u].x);
            *(float2*)(dst + 1 * HROW) = make_float2(hv[u].y, hv[u].y);
            *(float2*)(dst + 2 * HROW) = make_float2(hv[u].z, hv[u].z);
            *(float2*)(dst + 3 * HROW) = make_float2(hv[u].w, hv[u].w);
        }
        #pragma unroll
        for (int u = 0; u < 4; u++) {
            float* dst = Ws + w_soff[u];
            *(float2*)(dst + (w_jq[u] * 2 + 0) * 8) = make_float2(wv[u].x, wv[u].y);
            *(float2*)(dst + (w_jq[u] * 2 + 1) * 8) = make_float2(wv[u].z, wv[u].w);
        }
        __syncthreads();

        // ---- prefetch next chunk (LDG latency hidden behind compute)
        if (ci < 7) {
            #pragma unroll
            for (int u = 0; u < 2; u++) {
                h_gp[u] += KC;
                hv[u] = *(const float4*)(h_gp[u]);
            }
            #pragma unroll
            for (int u = 0; u < 4; u++) {
                w_gp[u] += (size_t)KC * G4_SZ;
                wv[u] = *(const float4*)(w_gp[u]);
            }
        }

        // ---- compute: 16 kk x 16 FFMA2 (+4 LDS.128)
        #pragma unroll
        for (int kk = 0; kk < KC; kk++) {
            ulonglong2 h01 = *(const ulonglong2*)(hb + kk * HROW);
            ulonglong2 h23 = *(const ulonglong2*)(hb + kk * HROW + 4);
            ulonglong2 w01 = *(const ulonglong2*)(wb + kk * WROW);
            ulonglong2 w23 = *(const ulonglong2*)(wb + kk * WROW + 4);
            u64 hh[4] = {h01.x, h01.y, h23.x, h23.y};
            u64 ww[4] = {w01.x, w01.y, w23.x, w23.y};
            #pragma unroll
            for (int i = 0; i < 4; i++)
                #pragma unroll
                for (int g = 0; g < 4; g++)
                    ffma2(acc[i][g], hh[i], ww[g]);
        }
    }

    // ---- k-split reduction through smem (padded stride: no 32-way conflict)
    __syncthreads();
    float* red = smem;  // [ks][slot(64) stride 34][32]
    #pragma unroll
    for (int i = 0; i < 4; i++)
        #pragma unroll
        for (int g = 0; g < 4; g++)
            *(u64*)(red + ks * 2176 + slot * 34 + i * 8 + g * 2) = acc[i][g];
    __syncthreads();

    // ---- fused epilogue: 2 (b,j) cells per thread
    #pragma unroll
    for (int u = 0; u < 2; u++) {
        int c       = u * 256 + t;      // 0..511 = 32 b x 16 j
        int b_local = c >> 4;
        int jl      = c & 15;
        int bg2 = b_local >> 2, b_i = b_local & 3;
        int jp2 = jl >> 1,      jd  = jl & 1;

        const float* p = red + (bg2 * 8 + jp2) * 34 + b_i * 8 + jd;
        float z[4];
        #pragma unroll
        for (int g = 0; g < 4; g++)
            z[g] = p[g * 2] + p[2176 + g * 2] + p[4352 + g * 2] + p[6528 + g * 2];

        int b = bm0 + b_local;
        int j = j0 + jl;
        const float* it = intern_t + (size_t)b * G4_SZ + j;
        float zc = z[0] + it[0];
        float zi = z[1] + it[512];
        float zf = z[2] + it[1024];
        float zo = z[3] + it[1536];

        float cin = tanhf(zc);
        float ig  = 1.f / (1.f + expf(-zi));
        float fg  = 1.f / (1.f + expf(-zf));
        float og  = 1.f / (1.f + expf(-zo));

        float m    = i_t[b];
        float cold = c_prev[(size_t)b * D_SZ + j];
        float cnew = m * (cold * fg + cin * ig) + (1.f - m) * cold;
        float y    = m * (og * tanhf(cnew));

        Y_t[(size_t)b * D_SZ + j] = y;
        C_t[(size_t)b * D_SZ + j] = cnew;
        if (d_fin) d_fin[(size_t)b * D_SZ + j] = cnew;
    }
}

// ---------------------------------------------------------------------------
// Launch: 1 GEMM + 512 sequential step kernels
// Inputs: X, Wf, Wr, bf, i, h0, c0. Output: Y[T,B,D] | C[T,B,D] | d[B,D]
// ---------------------------------------------------------------------------
extern "C" void kernel_launch(void* const* d_in, const int* in_sizes, int n_in,
                              void* d_out, int out_size)
{
    (void)in_sizes; (void)n_in; (void)out_size;
    const float* X  = (const float*)d_in[0];
    const float* Wf = (const float*)d_in[1];
    const float* Wr = (const float*)d_in[2];
    const float* bf = (const float*)d_in[3];
    const float* iv = (const float*)d_in[4];
    const float* h0 = (const float*)d_in[5];
    const float* c0 = (const float*)d_in[6];

    float* out  = (float*)d_out;
    float* Y    = out;
    float* C    = out + (size_t)T_STEPS * B_SZ * D_SZ;
    float* dfin = C   + (size_t)T_STEPS * B_SZ * D_SZ;

    dim3 g1(G4_SZ / 128, (T_STEPS * B_SZ) / 128);  // (16, 512)
    gemm_intern_kernel<<<g1, 256>>>(X, Wf, bf);

    dim3 g2(D_SZ / 16, B_SZ / 32);                 // (32, 4)
    for (int t = 0; t < T_STEPS; t++) {
        const float* hp = t ? (const float*)(Y + (size_t)(t - 1) * B_SZ * D_SZ) : h0;
        const float* cp = t ? (const float*)(C + (size_t)(t - 1) * B_SZ * D_SZ) : c0;
        lstm_step_kernel<<<g2, 256>>>(t, hp, cp, iv + (size_t)t * B_SZ, Wr,
                                      Y + (size_t)t * B_SZ * D_SZ,
                                      C + (size_t)t * B_SZ * D_SZ,
                                      (t == T_STEPS - 1) ? dfin : nullptr);
    }
}

// round 3
// speedup vs baseline: 1.2740x; 1.2740x over previous
#include <cuda_runtime.h>
#include <math.h>

#define T_STEPS 512
#define B_SZ    128
#define NI_SZ   512
#define D_SZ    512
#define G4_SZ   2048   // 4*D

typedef unsigned long long u64;

// Scratch (device globals: allocation-free rule workaround)
__device__ float g_intern[(size_t)T_STEPS * B_SZ * G4_SZ];
__device__ float g_hT[2][(size_t)D_SZ * B_SZ];   // transposed h mirror [k][b], ping-pong

__device__ __forceinline__ void ffma2(u64 &d, u64 a, u64 b) {
    asm("fma.rn.f32x2 %0, %1, %2, %0;" : "+l"(d) : "l"(a), "l"(b));
}
__device__ __forceinline__ u64 dup2(float f) {
    u64 d; asm("mov.b64 %0, {%1, %1};" : "=l"(d) : "f"(f)); return d;
}
__device__ __forceinline__ u64 add2(u64 a, u64 b) {
    u64 d; asm("add.rn.f32x2 %0, %1, %2;" : "=l"(d) : "l"(a), "l"(b)); return d;
}
__device__ __forceinline__ float2 unpack2(u64 a) {
    float2 f; asm("mov.b64 {%0, %1}, %2;" : "=f"(f.x), "=f"(f.y) : "l"(a)); return f;
}

// ---------------------------------------------------------------------------
// h0 transpose: g_hT[0][k*128+b] = h0[b*512+k]
// ---------------------------------------------------------------------------
__global__ __launch_bounds__(256)
void h0_transpose_kernel(const float* __restrict__ h0)
{
    int idx = blockIdx.x * 256 + threadIdx.x;   // 65536 total
    int k = idx >> 7, b = idx & 127;
    g_hT[0][idx] = h0[b * D_SZ + k];
}

// ---------------------------------------------------------------------------
// Phase 1: intern = X@Wf + bf, 128x128x8 tile, FFMA2 (j-pair packed accs)
// ---------------------------------------------------------------------------
__global__ __launch_bounds__(256)
void gemm_intern_kernel(const float* __restrict__ X,
                        const float* __restrict__ Wf,
                        const float* __restrict__ bf)
{
    __shared__ __align__(16) float As[8][128];
    __shared__ __align__(16) float Bs[8][128];

    const int t  = threadIdx.x;
    const int tx = t & 15;
    const int ty = t >> 4;
    const int m0 = blockIdx.y * 128;
    const int n0 = blockIdx.x * 128;

    const int arow = t >> 1, acol = (t & 1) * 4;
    const int brow = t >> 5, bcol = (t & 31) * 4;

    const float* Aptr = X  + (size_t)(m0 + arow) * NI_SZ + acol;
    const float* Bptr = Wf + (size_t)brow * G4_SZ + n0 + bcol;

    u64 acc[8][4];
    #pragma unroll
    for (int i = 0; i < 8; i++)
        #pragma unroll
        for (int j = 0; j < 4; j++) acc[i][j] = 0ull;

    for (int k0 = 0; k0 < NI_SZ; k0 += 8) {
        float4 av = *(const float4*)(Aptr + k0);
        float4 bv = *(const float4*)(Bptr + (size_t)k0 * G4_SZ);
        __syncthreads();
        As[acol + 0][arow] = av.x;
        As[acol + 1][arow] = av.y;
        As[acol + 2][arow] = av.z;
        As[acol + 3][arow] = av.w;
        *(float4*)&Bs[brow][bcol] = bv;
        __syncthreads();
        #pragma unroll
        for (int k = 0; k < 8; k++) {
            float4 a0 = *(const float4*)&As[k][ty * 4];
            float4 a1 = *(const float4*)&As[k][64 + ty * 4];
            ulonglong2 bA = *(const ulonglong2*)&Bs[k][tx * 4];
            ulonglong2 bB = *(const ulonglong2*)&Bs[k][64 + tx * 4];
            u64 ad[8] = {dup2(a0.x), dup2(a0.y), dup2(a0.z), dup2(a0.w),
                         dup2(a1.x), dup2(a1.y), dup2(a1.z), dup2(a1.w)};
            #pragma unroll
            for (int i = 0; i < 8; i++) {
                ffma2(acc[i][0], ad[i], bA.x);
                ffma2(acc[i][1], ad[i], bA.y);
                ffma2(acc[i][2], ad[i], bB.x);
                ffma2(acc[i][3], ad[i], bB.y);
            }
        }
    }

    float4 bias0 = *(const float4*)&bf[n0 + tx * 4];
    float4 bias1 = *(const float4*)&bf[n0 + 64 + tx * 4];
    #pragma unroll
    for (int i = 0; i < 8; i++) {
        int m = m0 + (i < 4 ? ty * 4 + i : 64 + ty * 4 + (i - 4));
        float* out = g_intern + (size_t)m * G4_SZ + n0;
        float2 p0 = unpack2(acc[i][0]), p1 = unpack2(acc[i][1]);
        float2 p2 = unpack2(acc[i][2]), p3 = unpack2(acc[i][3]);
        float4 v0 = make_float4(p0.x + bias0.x, p0.y + bias0.y,
                                p1.x + bias0.z, p1.y + bias0.w);
        float4 v1 = make_float4(p2.x + bias1.x, p2.y + bias1.y,
                                p3.x + bias1.z, p3.y + bias1.w);
        *(float4*)(out + tx * 4)      = v0;
        *(float4*)(out + 64 + tx * 4) = v1;
    }
}

// ---------------------------------------------------------------------------
// Phase 2: one LSTM step.
// CTA: 32 b x 16 j x 4 g; 256 thr = 8 warps = 8 k-splits (k = m*8+ks within
// chunks of 64). Thread tile: 8b (4 packed pairs) x 2j x 4g = 32 u64 accs.
// h pairs natural from k-major smem (broadcast, conflict-free); w scalars
// LDS.128 (XOR-skewed, conflict-free) + MOV-dup. Epilogue writes Y, C, and
// the transposed h mirror for the next step (via smem transpose).
// ---------------------------------------------------------------------------
#define HROW 36   // [k][32b + pad]
#define WROW 68   // [k][8 jp-groups of 8, skewed]

__global__ __launch_bounds__(256)
void lstm_step_kernel(int tstep,
                      const float* __restrict__ hT_in,
                      float* __restrict__ hT_out,
                      const float* __restrict__ c_prev,
                      const float* __restrict__ i_t,
                      const float* __restrict__ Wr,
                      float* __restrict__ Y_t,
                      float* __restrict__ C_t,
                      float* __restrict__ d_fin)
{
    // staging: Hs 64*36=2304 | Ws 64*68=4352  (6656 f)
    // reduction reuse: 4 * 32*68 = 8704 f ; ybuf on top: 544 f
    __shared__ __align__(16) float smem[8704 + 544];
    float* Hs   = smem;
    float* Ws   = smem + 2304;
    float* red  = smem;
    float* ybuf = smem + 8704;

    const float* intern_t = g_intern + (size_t)tstep * (B_SZ * G4_SZ);

    const int t    = threadIdx.x;
    const int ks   = t >> 5;          // warp = k-split
    const int lane = t & 31;
    const int bg   = lane >> 3;       // b-group of 8
    const int jp   = lane & 7;        // j-pair
    const int j0   = blockIdx.x * 16;
    const int bm0  = blockIdx.y * 32;
    const int woff = jp * 8 + (jp >> 2) * 4;   // skewed group base

    // ---- h staging map: thread -> 2 rows (k) of 4 b's, fully coalesced LDG
    const int h_kr = t >> 3;              // 0..31  (k row pair index)
    const int h_bq = (t & 7) * 4;         // b quad
    const float* hgp = hT_in + (size_t)(h_kr * 2) * B_SZ + bm0 + h_bq;

    // ---- w staging map: 4 float4 per thread per chunk
    const float* wgp[4];
    int w_offA[4], w_offB[4];
    #pragma unroll
    for (int u = 0; u < 4; u++) {
        int idx = u * 256 + t;
        int kk2 = idx >> 4;               // 0..63 row in chunk
        int rem = idx & 15;
        int g = rem >> 2, jq = rem & 3;
        wgp[u] = Wr + (size_t)kk2 * G4_SZ + g * D_SZ + j0 + jq * 4;
        int jpA = jq * 2, jpB = jq * 2 + 1;
        w_offA[u] = kk2 * WROW + jpA * 8 + (jpA >> 2) * 4 + g * 2;
        w_offB[u] = kk2 * WROW + jpB * 8 + (jpB >> 2) * 4 + g * 2;
    }

    u64 acc[4][8];
    #pragma unroll
    for (int i = 0; i < 4; i++)
        #pragma unroll
        for (int j = 0; j < 8; j++) acc[i][j] = 0ull;

    // preload chunk 0
    float4 hv0 = *(const float4*)(hgp);
    float4 hv1 = *(const float4*)(hgp + B_SZ);
    float4 wv[4];
    #pragma unroll
    for (int u = 0; u < 4; u++) wv[u] = *(const float4*)(wgp[u]);

    for (int ci = 0; ci < 8; ci++) {
        __syncthreads();
        *(float4*)(Hs + (h_kr * 2 + 0) * HROW + h_bq) = hv0;
        *(float4*)(Hs + (h_kr * 2 + 1) * HROW + h_bq) = hv1;
        #pragma unroll
        for (int u = 0; u < 4; u++) {
            *(float2*)(Ws + w_offA[u]) = make_float2(wv[u].x, wv[u].y);
            *(float2*)(Ws + w_offB[u]) = make_float2(wv[u].z, wv[u].w);
        }
        __syncthreads();

        if (ci < 7) {
            hgp += 64 * B_SZ;
            hv0 = *(const float4*)(hgp);
            hv1 = *(const float4*)(hgp + B_SZ);
            #pragma unroll
            for (int u = 0; u < 4; u++) {
                wgp[u] += (size_t)64 * G4_SZ;
                wv[u] = *(const float4*)(wgp[u]);
            }
        }

        #pragma unroll
        for (int m = 0; m < 8; m++) {
            int kc = m * 8 + ks;
            ulonglong2 hA = *(const ulonglong2*)(Hs + kc * HROW + bg * 8);
            ulonglong2 hB = *(const ulonglong2*)(Hs + kc * HROW + bg * 8 + 4);
            float4 wA = *(const float4*)(Ws + kc * WROW + woff);
            float4 wB = *(const float4*)(Ws + kc * WROW + woff + 4);
            u64 hp[4] = {hA.x, hA.y, hB.x, hB.y};
            u64 wd[8] = {dup2(wA.x), dup2(wA.y), dup2(wA.z), dup2(wA.w),
                         dup2(wB.x), dup2(wB.y), dup2(wB.z), dup2(wB.w)};
            #pragma unroll
            for (int bp = 0; bp < 4; bp++)
                #pragma unroll
                for (int cc = 0; cc < 8; cc++)
                    ffma2(acc[bp][cc], hp[bp], wd[cc]);
        }
    }

    // ---- 8 -> 4 -> epilogue reduction (fits 48KB static smem)
    __syncthreads();
    {
        float* entry = red + lane * WROW;   // [p][slot(32)*68 + ...]
        if (ks >= 4) {
            float* p = entry + (ks - 4) * 2176;
            #pragma unroll
            for (int bp = 0; bp < 4; bp++)
                #pragma unroll
                for (int ce = 0; ce < 4; ce++)
                    *(ulonglong2*)(p + bp * 16 + ce * 4) =
                        make_ulonglong2(acc[bp][ce * 2], acc[bp][ce * 2 + 1]);
        }
    }
    __syncthreads();
    {
        float* entry = red + lane * WROW;
        if (ks < 4) {
            float* p = entry + ks * 2176;
            #pragma unroll
            for (int bp = 0; bp < 4; bp++)
                #pragma unroll
                for (int ce = 0; ce < 4; ce++) {
                    ulonglong2 v = *(ulonglong2*)(p + bp * 16 + ce * 4);
                    v.x = add2(v.x, acc[bp][ce * 2]);
                    v.y = add2(v.y, acc[bp][ce * 2 + 1]);
                    *(ulonglong2*)(p + bp * 16 + ce * 4) = v;
                }
        }
    }
    __syncthreads();

    // ---- fused epilogue (mapping A: b-major cells, coalesced Y/C/intern)
    #pragma unroll
    for (int u = 0; u < 2; u++) {
        int c   = u * 256 + t;           // 0..511 = 32 b x 16 j
        int b_l = c >> 4;
        int jl  = c & 15;
        int slot = (b_l >> 3) * 8 + (jl >> 1);
        int eoff = slot * WROW + ((b_l & 7) >> 1) * 16 + (jl & 1) * 2 + (b_l & 1);

        float z[4];
        #pragma unroll
        for (int g = 0; g < 4; g++)
            z[g] = red[eoff + g * 4] + red[2176 + eoff + g * 4]
                 + red[4352 + eoff + g * 4] + red[6528 + eoff + g * 4];

        int b = bm0 + b_l;
        int j = j0 + jl;
        const float* it = intern_t + (size_t)b * G4_SZ + j;
        float zc = z[0] + it[0];
        float zi = z[1] + it[512];
        float zf = z[2] + it[1024];
        float zo = z[3] + it[1536];

        zc = fminf(fmaxf(zc, -30.f), 30.f);
        float ec  = __expf(-2.f * zc);
        float cin = (1.f - ec) / (1.f + ec);
        float ig  = 1.f / (1.f + __expf(-zi));
        float fg  = 1.f / (1.f + __expf(-zf));
        float og  = 1.f / (1.f + __expf(-zo));

        float m    = i_t[b];
        float cold = c_prev[(size_t)b * D_SZ + j];
        float cnew = m * (cold * fg + cin * ig) + (1.f - m) * cold;
        float ct   = fminf(fmaxf(cnew, -30.f), 30.f);
        float e2   = __expf(-2.f * ct);
        float y    = m * (og * (1.f - e2) / (1.f + e2));

        Y_t[(size_t)b * D_SZ + j] = y;
        C_t[(size_t)b * D_SZ + j] = cnew;
        if (d_fin) d_fin[(size_t)b * D_SZ + j] = cnew;
        ybuf[b_l * 17 + jl] = y;
    }
    __syncthreads();

    // ---- write transposed h mirror (mapping B: j-major, coalesced in b)
    #pragma unroll
    for (int u = 0; u < 2; u++) {
        int c = u * 256 + t;
        int jl2 = c >> 5;
        int b2  = c & 31;
        hT_out[(size_t)(j0 + jl2) * B_SZ + bm0 + b2] = ybuf[b2 * 17 + jl2];
    }
}

// ---------------------------------------------------------------------------
// Launch. Inputs: X, Wf, Wr, bf, i, h0, c0. Output: Y[T,B,D]|C[T,B,D]|d[B,D]
// ---------------------------------------------------------------------------
extern "C" void kernel_launch(void* const* d_in, const int* in_sizes, int n_in,
                              void* d_out, int out_size)
{
    (void)in_sizes; (void)n_in; (void)out_size;
    const float* X  = (const float*)d_in[0];
    const float* Wf = (const float*)d_in[1];
    const float* Wr = (const float*)d_in[2];
    const float* bf = (const float*)d_in[3];
    const float* iv = (const float*)d_in[4];
    const float* h0 = (const float*)d_in[5];
    const float* c0 = (const float*)d_in[6];

    float* out  = (float*)d_out;
    float* Y    = out;
    float* C    = out + (size_t)T_STEPS * B_SZ * D_SZ;
    float* dfin = C   + (size_t)T_STEPS * B_SZ * D_SZ;

    float* hT0; cudaGetSymbolAddress((void**)&hT0, g_hT);

    h0_transpose_kernel<<<256, 256>>>(h0);

    dim3 g1(G4_SZ / 128, (T_STEPS * B_SZ) / 128);  // (16, 512)
    gemm_intern_kernel<<<g1, 256>>>(X, Wf, bf);

    dim3 g2(D_SZ / 16, B_SZ / 32);                 // (32, 4)
    for (int t = 0; t < T_STEPS; t++) {
        const float* hin = hT0 + (size_t)(t & 1) * (D_SZ * B_SZ);
        float*       hot = hT0 + (size_t)((t + 1) & 1) * (D_SZ * B_SZ);
        const float* cp  = t ? (const float*)(C + (size_t)(t - 1) * B_SZ * D_SZ) : c0;
        lstm_step_kernel<<<g2, 256>>>(t, hin, hot, cp, iv + (size_t)t * B_SZ, Wr,
                                      Y + (size_t)t * B_SZ * D_SZ,
                                      C + (size_t)t * B_SZ * D_SZ,
                                      (t == T_STEPS - 1) ? dfin : nullptr);
    }
}

// round 4
// speedup vs baseline: 1.3466x; 1.0570x over previous
#include <cuda_runtime.h>
#include <math.h>

#define T_STEPS 512
#define B_SZ    128
#define NI_SZ   512
#define D_SZ    512
#define G4_SZ   2048   // 4*D

typedef unsigned long long u64;

// Scratch (device globals: allocation-free rule workaround)
__device__ float g_intern[(size_t)T_STEPS * B_SZ * G4_SZ];
__device__ float g_hT[2][(size_t)D_SZ * B_SZ];   // transposed h mirror [k][b], ping-pong

__device__ __forceinline__ void ffma2(u64 &d, u64 a, u64 b) {
    asm("fma.rn.f32x2 %0, %1, %2, %0;" : "+l"(d) : "l"(a), "l"(b));
}
__device__ __forceinline__ u64 dup2(float f) {
    u64 d; asm("mov.b64 %0, {%1, %1};" : "=l"(d) : "f"(f)); return d;
}
__device__ __forceinline__ u64 add2(u64 a, u64 b) {
    u64 d; asm("add.rn.f32x2 %0, %1, %2;" : "=l"(d) : "l"(a), "l"(b)); return d;
}
__device__ __forceinline__ float2 unpack2(u64 a) {
    float2 f; asm("mov.b64 {%0, %1}, %2;" : "=f"(f.x), "=f"(f.y) : "l"(a)); return f;
}

// ---------------------------------------------------------------------------
// h0 transpose: g_hT[0][k*128+b] = h0[b*512+k]
// ---------------------------------------------------------------------------
__global__ __launch_bounds__(256)
void h0_transpose_kernel(const float* __restrict__ h0)
{
    int idx = blockIdx.x * 256 + threadIdx.x;   // 65536 total
    int k = idx >> 7, b = idx & 127;
    g_hT[0][idx] = h0[b * D_SZ + k];
}

// ---------------------------------------------------------------------------
// Phase 1: intern = X@Wf + bf, 128x128x8 tile, FFMA2 (unchanged from R3)
// ---------------------------------------------------------------------------
__global__ __launch_bounds__(256)
void gemm_intern_kernel(const float* __restrict__ X,
                        const float* __restrict__ Wf,
                        const float* __restrict__ bf)
{
    __shared__ __align__(16) float As[8][128];
    __shared__ __align__(16) float Bs[8][128];

    const int t  = threadIdx.x;
    const int tx = t & 15;
    const int ty = t >> 4;
    const int m0 = blockIdx.y * 128;
    const int n0 = blockIdx.x * 128;

    const int arow = t >> 1, acol = (t & 1) * 4;
    const int brow = t >> 5, bcol = (t & 31) * 4;

    const float* Aptr = X  + (size_t)(m0 + arow) * NI_SZ + acol;
    const float* Bptr = Wf + (size_t)brow * G4_SZ + n0 + bcol;

    u64 acc[8][4];
    #pragma unroll
    for (int i = 0; i < 8; i++)
        #pragma unroll
        for (int j = 0; j < 4; j++) acc[i][j] = 0ull;

    for (int k0 = 0; k0 < NI_SZ; k0 += 8) {
        float4 av = *(const float4*)(Aptr + k0);
        float4 bv = *(const float4*)(Bptr + (size_t)k0 * G4_SZ);
        __syncthreads();
        As[acol + 0][arow] = av.x;
        As[acol + 1][arow] = av.y;
        As[acol + 2][arow] = av.z;
        As[acol + 3][arow] = av.w;
        *(float4*)&Bs[brow][bcol] = bv;
        __syncthreads();
        #pragma unroll
        for (int k = 0; k < 8; k++) {
            float4 a0 = *(const float4*)&As[k][ty * 4];
            float4 a1 = *(const float4*)&As[k][64 + ty * 4];
            ulonglong2 bA = *(const ulonglong2*)&Bs[k][tx * 4];
            ulonglong2 bB = *(const ulonglong2*)&Bs[k][64 + tx * 4];
            u64 ad[8] = {dup2(a0.x), dup2(a0.y), dup2(a0.z), dup2(a0.w),
                         dup2(a1.x), dup2(a1.y), dup2(a1.z), dup2(a1.w)};
            #pragma unroll
            for (int i = 0; i < 8; i++) {
                ffma2(acc[i][0], ad[i], bA.x);
                ffma2(acc[i][1], ad[i], bA.y);
                ffma2(acc[i][2], ad[i], bB.x);
                ffma2(acc[i][3], ad[i], bB.y);
            }
        }
    }

    float4 bias0 = *(const float4*)&bf[n0 + tx * 4];
    float4 bias1 = *(const float4*)&bf[n0 + 64 + tx * 4];
    #pragma unroll
    for (int i = 0; i < 8; i++) {
        int m = m0 + (i < 4 ? ty * 4 + i : 64 + ty * 4 + (i - 4));
        float* out = g_intern + (size_t)m * G4_SZ + n0;
        float2 p0 = unpack2(acc[i][0]), p1 = unpack2(acc[i][1]);
        float2 p2 = unpack2(acc[i][2]), p3 = unpack2(acc[i][3]);
        float4 v0 = make_float4(p0.x + bias0.x, p0.y + bias0.y,
                                p1.x + bias0.z, p1.y + bias0.w);
        float4 v1 = make_float4(p2.x + bias1.x, p2.y + bias1.y,
                                p3.x + bias1.z, p3.y + bias1.w);
        *(float4*)(out + tx * 4)      = v0;
        *(float4*)(out + 64 + tx * 4) = v1;
    }
}

// ---------------------------------------------------------------------------
// Phase 2: one LSTM step. 512 threads (16 warps, 4/SMSP for latency hiding).
// CTA tile: 32 b x 16 j x 4 g. k-split 8 (2 warps per split, 64 k each).
// Thread tile: 4b x 1 j-pair x 4g = 16 packed-f32x2 accumulators (j-packed:
// w pairs native from smem, h scalars dup'd via 1 MOV each).
// Per kk per thread: 3 LDS.128 + 4 MOV + 16 FFMA2 -> fma-pipe bound.
// ---------------------------------------------------------------------------
#define HROW 36   // [k][32 b + pad]
#define WROW 68   // [k][8 jp x 4 g u64, XOR-skewed]

__global__ __launch_bounds__(512)
void lstm_step_kernel(int tstep,
                      const float* __restrict__ hT_in,
                      float* __restrict__ hT_out,
                      const float* __restrict__ c_prev,
                      const float* __restrict__ i_t,
                      const float* __restrict__ Wr,
                      float* __restrict__ Y_t,
                      float* __restrict__ C_t,
                      float* __restrict__ d_fin)
{
    // staging: Hs 64*36=2304 | Ws 64*68=4352 (6656 f)
    // reduction reuse: 4 * 64*36 = 9216 f ; ybuf on top: 544 f
    __shared__ __align__(16) float smem[9216 + 544];
    float* Hs   = smem;
    float* Ws   = smem + 2304;
    float* red  = smem;
    float* ybuf = smem + 9216;

    const float* intern_t = g_intern + (size_t)tstep * (B_SZ * G4_SZ);

    const int t    = threadIdx.x;
    const int ks   = t >> 6;          // k-split (64 k each, 2 warps)
    const int slot = t & 63;
    const int bg   = slot >> 3;       // b-group of 4 (0..7)
    const int jp   = slot & 7;        // j-pair (0..7)
    const int j0   = blockIdx.x * 16;
    const int bm0  = blockIdx.y * 32;
    const int woff = jp * 8 + (jp >> 2) * 4;   // skewed u64-group base (floats)

    // ---- h staging: 1 float4/thread/chunk, coalesced from k-major hT
    const int h_kk = t >> 3;              // 0..63 (k row in chunk)
    const int h_bq = (t & 7) * 4;         // b quad
    const float* hgp = hT_in + (size_t)h_kk * B_SZ + bm0 + h_bq;

    // ---- w staging: 2 float4/thread/chunk
    const float* wgp[2];
    int w_offA[2], w_offB[2];
    #pragma unroll
    for (int u = 0; u < 2; u++) {
        int idx = u * 512 + t;
        int kk2 = idx >> 4;               // 0..63 row in chunk
        int rem = idx & 15;
        int g = rem >> 2, jq = rem & 3;
        wgp[u] = Wr + (size_t)kk2 * G4_SZ + g * D_SZ + j0 + jq * 4;
        int jpA = jq * 2, jpB = jq * 2 + 1;
        w_offA[u] = kk2 * WROW + jpA * 8 + (jpA >> 2) * 4 + g * 2;
        w_offB[u] = kk2 * WROW + jpB * 8 + (jpB >> 2) * 4 + g * 2;
    }

    u64 acc[4][4];
    #pragma unroll
    for (int i = 0; i < 4; i++)
        #pragma unroll
        for (int g = 0; g < 4; g++) acc[i][g] = 0ull;

    // preload chunk 0
    float4 hv = *(const float4*)(hgp);
    float4 wv[2];
    #pragma unroll
    for (int u = 0; u < 2; u++) wv[u] = *(const float4*)(wgp[u]);

    for (int ci = 0; ci < 8; ci++) {
        __syncthreads();
        *(float4*)(Hs + h_kk * HROW + h_bq) = hv;
        #pragma unroll
        for (int u = 0; u < 2; u++) {
            *(float2*)(Ws + w_offA[u]) = make_float2(wv[u].x, wv[u].y);
            *(float2*)(Ws + w_offB[u]) = make_float2(wv[u].z, wv[u].w);
        }
        __syncthreads();

        if (ci < 7) {
            hgp += 64 * B_SZ;
            hv = *(const float4*)(hgp);
            #pragma unroll
            for (int u = 0; u < 2; u++) {
                wgp[u] += (size_t)64 * G4_SZ;
                wv[u] = *(const float4*)(wgp[u]);
            }
        }

        // ---- compute: 8 kk per split per chunk; 3 LDS.128 + 16 FFMA2 each
        #pragma unroll
        for (int m = 0; m < 8; m++) {
            int kc = m * 8 + ks;
            float4 hq = *(const float4*)(Hs + kc * HROW + bg * 4);
            ulonglong2 wA = *(const ulonglong2*)(Ws + kc * WROW + woff);
            ulonglong2 wB = *(const ulonglong2*)(Ws + kc * WROW + woff + 4);
            u64 hd[4] = {dup2(hq.x), dup2(hq.y), dup2(hq.z), dup2(hq.w)};
            u64 wd[4] = {wA.x, wA.y, wB.x, wB.y};
            #pragma unroll
            for (int i = 0; i < 4; i++)
                #pragma unroll
                for (int g = 0; g < 4; g++)
                    ffma2(acc[i][g], hd[i], wd[g]);
        }
    }

    // ---- k-split reduction 8 -> 4 -> epilogue
    __syncthreads();
    if (ks >= 4) {
        float* p = red + (ks - 4) * 2304 + slot * 36;
        #pragma unroll
        for (int i = 0; i < 4; i++) {
            *(ulonglong2*)(p + i * 8)     = make_ulonglong2(acc[i][0], acc[i][1]);
            *(ulonglong2*)(p + i * 8 + 4) = make_ulonglong2(acc[i][2], acc[i][3]);
        }
    }
    __syncthreads();
    if (ks < 4) {
        float* p = red + ks * 2304 + slot * 36;
        #pragma unroll
        for (int i = 0; i < 4; i++) {
            ulonglong2 v0 = *(ulonglong2*)(p + i * 8);
            ulonglong2 v1 = *(ulonglong2*)(p + i * 8 + 4);
            v0.x = add2(v0.x, acc[i][0]);
            v0.y = add2(v0.y, acc[i][1]);
            v1.x = add2(v1.x, acc[i][2]);
            v1.y = add2(v1.y, acc[i][3]);
            *(ulonglong2*)(p + i * 8)     = v0;
            *(ulonglong2*)(p + i * 8 + 4) = v1;
        }
    }
    __syncthreads();

    // ---- fused epilogue: exactly one (b,j) cell per thread
    {
        int b_l = t >> 4;
        int jl  = t & 15;
        int slot_e = (b_l >> 2) * 8 + (jl >> 1);
        int eoff   = slot_e * 36 + (b_l & 3) * 8 + (jl & 1);

        float z[4];
        #pragma unroll
        for (int g = 0; g < 4; g++)
            z[g] = red[eoff + g * 2] + red[2304 + eoff + g * 2]
                 + red[4608 + eoff + g * 2] + red[6912 + eoff + g * 2];

        int b = bm0 + b_l;
        int j = j0 + jl;
        const float* it = intern_t + (size_t)b * G4_SZ + j;
        float zc = z[0] + it[0];
        float zi = z[1] + it[512];
        float zf = z[2] + it[1024];
        float zo = z[3] + it[1536];

        zc = fminf(fmaxf(zc, -30.f), 30.f);
        float ec  = __expf(-2.f * zc);
        float cin = (1.f - ec) / (1.f + ec);
        float ig  = 1.f / (1.f + __expf(-zi));
        float fg  = 1.f / (1.f + __expf(-zf));
        float og  = 1.f / (1.f + __expf(-zo));

        float m    = i_t[b];
        float cold = c_prev[(size_t)b * D_SZ + j];
        float cnew = m * (cold * fg + cin * ig) + (1.f - m) * cold;
        float ct   = fminf(fmaxf(cnew, -30.f), 30.f);
        float e2   = __expf(-2.f * ct);
        float y    = m * (og * (1.f - e2) / (1.f + e2));

        Y_t[(size_t)b * D_SZ + j] = y;
        C_t[(size_t)b * D_SZ + j] = cnew;
        if (d_fin) d_fin[(size_t)b * D_SZ + j] = cnew;
        ybuf[b_l * 17 + jl] = y;
    }
    __syncthreads();

    // ---- write transposed h mirror for next step (coalesced in b)
    {
        int jl2 = t >> 5;
        int b2  = t & 31;
        hT_out[(size_t)(j0 + jl2) * B_SZ + bm0 + b2] = ybuf[b2 * 17 + jl2];
    }
}

// ---------------------------------------------------------------------------
// Launch. Inputs: X, Wf, Wr, bf, i, h0, c0. Output: Y[T,B,D]|C[T,B,D]|d[B,D]
// ---------------------------------------------------------------------------
extern "C" void kernel_launch(void* const* d_in, const int* in_sizes, int n_in,
                              void* d_out, int out_size)
{
    (void)in_sizes; (void)n_in; (void)out_size;
    const float* X  = (const float*)d_in[0];
    const float* Wf = (const float*)d_in[1];
    const float* Wr = (const float*)d_in[2];
    const float* bf = (const float*)d_in[3];
    const float* iv = (const float*)d_in[4];
    const float* h0 = (const float*)d_in[5];
    const float* c0 = (const float*)d_in[6];

    float* out  = (float*)d_out;
    float* Y    = out;
    float* C    = out + (size_t)T_STEPS * B_SZ * D_SZ;
    float* dfin = C   + (size_t)T_STEPS * B_SZ * D_SZ;

    float* hT0; cudaGetSymbolAddress((void**)&hT0, g_hT);

    h0_transpose_kernel<<<256, 256>>>(h0);

    dim3 g1(G4_SZ / 128, (T_STEPS * B_SZ) / 128);  // (16, 512)
    gemm_intern_kernel<<<g1, 256>>>(X, Wf, bf);

    dim3 g2(D_SZ / 16, B_SZ / 32);                 // (32, 4)
    for (int t = 0; t < T_STEPS; t++) {
        const float* hin = hT0 + (size_t)(t & 1) * (D_SZ * B_SZ);
        float*       hot = hT0 + (size_t)((t + 1) & 1) * (D_SZ * B_SZ);
        const float* cp  = t ? (const float*)(C + (size_t)(t - 1) * B_SZ * D_SZ) : c0;
        lstm_step_kernel<<<g2, 512>>>(t, hin, hot, cp, iv + (size_t)t * B_SZ, Wr,
                                      Y + (size_t)t * B_SZ * D_SZ,
                                      C + (size_t)t * B_SZ * D_SZ,
                                      (t == T_STEPS - 1) ? dfin : nullptr);
    }
}

// round 5
// speedup vs baseline: 1.4850x; 1.1027x over previous
#include <cuda_runtime.h>
#include <math.h>

#define T_STEPS 512
#define B_SZ    128
#define NI_SZ   512
#define D_SZ    512
#define G4_SZ   2048   // 4*D

typedef unsigned long long u64;

// Scratch (device globals: allocation-free rule workaround)
__device__ float g_intern[(size_t)T_STEPS * B_SZ * G4_SZ];
__device__ float g_hT[2][(size_t)D_SZ * B_SZ];   // transposed h mirror [k][b], ping-pong
__device__ unsigned g_bar_cnt;
__device__ unsigned g_bar_gen;

__device__ __forceinline__ void ffma2(u64 &d, u64 a, u64 b) {
    asm("fma.rn.f32x2 %0, %1, %2, %0;" : "+l"(d) : "l"(a), "l"(b));
}
__device__ __forceinline__ u64 dup2(float f) {
    u64 d; asm("mov.b64 %0, {%1, %1};" : "=l"(d) : "f"(f)); return d;
}
__device__ __forceinline__ u64 add2(u64 a, u64 b) {
    u64 d; asm("add.rn.f32x2 %0, %1, %2;" : "=l"(d) : "l"(a), "l"(b)); return d;
}
__device__ __forceinline__ float2 unpack2(u64 a) {
    float2 f; asm("mov.b64 {%0, %1}, %2;" : "=f"(f.x), "=f"(f.y) : "l"(a)); return f;
}

// ---------------------------------------------------------------------------
// h0 transpose: g_hT[0][k*128+b] = h0[b*512+k]
// ---------------------------------------------------------------------------
__global__ __launch_bounds__(256)
void h0_transpose_kernel(const float* __restrict__ h0)
{
    int idx = blockIdx.x * 256 + threadIdx.x;   // 65536 total
    int k = idx >> 7, b = idx & 127;
    g_hT[0][idx] = h0[b * D_SZ + k];
}

// ---------------------------------------------------------------------------
// Phase 1: intern = X@Wf + bf, 128x128x8 tile, FFMA2 (unchanged)
// ---------------------------------------------------------------------------
__global__ __launch_bounds__(256)
void gemm_intern_kernel(const float* __restrict__ X,
                        const float* __restrict__ Wf,
                        const float* __restrict__ bf)
{
    __shared__ __align__(16) float As[8][128];
    __shared__ __align__(16) float Bs[8][128];

    const int t  = threadIdx.x;
    const int tx = t & 15;
    const int ty = t >> 4;
    const int m0 = blockIdx.y * 128;
    const int n0 = blockIdx.x * 128;

    const int arow = t >> 1, acol = (t & 1) * 4;
    const int brow = t >> 5, bcol = (t & 31) * 4;

    const float* Aptr = X  + (size_t)(m0 + arow) * NI_SZ + acol;
    const float* Bptr = Wf + (size_t)brow * G4_SZ + n0 + bcol;

    u64 acc[8][4];
    #pragma unroll
    for (int i = 0; i < 8; i++)
        #pragma unroll
        for (int j = 0; j < 4; j++) acc[i][j] = 0ull;

    for (int k0 = 0; k0 < NI_SZ; k0 += 8) {
        float4 av = *(const float4*)(Aptr + k0);
        float4 bv = *(const float4*)(Bptr + (size_t)k0 * G4_SZ);
        __syncthreads();
        As[acol + 0][arow] = av.x;
        As[acol + 1][arow] = av.y;
        As[acol + 2][arow] = av.z;
        As[acol + 3][arow] = av.w;
        *(float4*)&Bs[brow][bcol] = bv;
        __syncthreads();
        #pragma unroll
        for (int k = 0; k < 8; k++) {
            float4 a0 = *(const float4*)&As[k][ty * 4];
            float4 a1 = *(const float4*)&As[k][64 + ty * 4];
            ulonglong2 bA = *(const ulonglong2*)&Bs[k][tx * 4];
            ulonglong2 bB = *(const ulonglong2*)&Bs[k][64 + tx * 4];
            u64 ad[8] = {dup2(a0.x), dup2(a0.y), dup2(a0.z), dup2(a0.w),
                         dup2(a1.x), dup2(a1.y), dup2(a1.z), dup2(a1.w)};
            #pragma unroll
            for (int i = 0; i < 8; i++) {
                ffma2(acc[i][0], ad[i], bA.x);
                ffma2(acc[i][1], ad[i], bA.y);
                ffma2(acc[i][2], ad[i], bB.x);
                ffma2(acc[i][3], ad[i], bB.y);
            }
        }
    }

    float4 bias0 = *(const float4*)&bf[n0 + tx * 4];
    float4 bias1 = *(const float4*)&bf[n0 + 64 + tx * 4];
    #pragma unroll
    for (int i = 0; i < 8; i++) {
        int m = m0 + (i < 4 ? ty * 4 + i : 64 + ty * 4 + (i - 4));
        float* out = g_intern + (size_t)m * G4_SZ + n0;
        float2 p0 = unpack2(acc[i][0]), p1 = unpack2(acc[i][1]);
        float2 p2 = unpack2(acc[i][2]), p3 = unpack2(acc[i][3]);
        float4 v0 = make_float4(p0.x + bias0.x, p0.y + bias0.y,
                                p1.x + bias0.z, p1.y + bias0.w);
        float4 v1 = make_float4(p2.x + bias1.x, p2.y + bias1.y,
                                p3.x + bias1.z, p3.y + bias1.w);
        *(float4*)(out + tx * 4)      = v0;
        *(float4*)(out + 64 + tx * 4) = v1;
    }
}

// ---------------------------------------------------------------------------
// Phase 2: persistent LSTM kernel. 128 CTAs (1/SM, co-resident), 512 threads.
// Wr slice (512k x 64 cols, skewed) lives in smem for ALL 512 steps.
// Per step: stage full h (512k x 32b) to smem, 64-iter LDS+FFMA2 mainloop
// (k-split 8), smem reduction, fused epilogue (c in registers), write Y/C/hT,
// gmem-atomic grid barrier.
// ---------------------------------------------------------------------------
#define THREADS 512
#define WROW 68                    // [k][8 jp x 4 g u64, XOR-skewed]
#define HROW 36                    // [k][32 b + pad]
#define WR_F (512 * WROW)          // 34816 floats
#define H_F  (512 * HROW)          // 18432 floats
#define SMEM_F (WR_F + H_F + 544)  // 53792 floats = 215168 bytes

__global__ __launch_bounds__(THREADS, 1)
void lstm_persistent_kernel(const float* __restrict__ hT0,
                            const float* __restrict__ c0,
                            const float* __restrict__ iv,
                            const float* __restrict__ Wr,
                            float* __restrict__ Y,
                            float* __restrict__ C,
                            float* __restrict__ d_fin)
{
    extern __shared__ __align__(16) float smem[];
    float* Ws   = smem;                 // Wr slice, persistent
    float* Hs   = smem + WR_F;          // h buffer (aliased by reduction)
    float* red  = Hs;
    float* ybuf = smem + WR_F + H_F;

    const int t    = threadIdx.x;
    const int bid  = blockIdx.x;        // 0..127
    const int j0   = (bid & 31) * 16;
    const int bm0  = (bid >> 5) * 32;

    const int ks   = t >> 6;            // k-split (64 k each)
    const int slot = t & 63;
    const int bg   = slot >> 3;         // b-group of 4 (0..7)
    const int jp   = slot & 7;          // j-pair
    const int woff = jp * 8 + (jp >> 2) * 4;

    // epilogue cell (fixed per thread; c lives in a register across steps)
    const int b_l = t >> 4, jl = t & 15;
    const int b_g = bm0 + b_l, j_g = j0 + jl;
    const int eoff = ((b_l >> 2) * 8 + (jl >> 1)) * 36 + (b_l & 3) * 8 + (jl & 1);
    float c_reg = __ldcg(c0 + (size_t)b_g * D_SZ + j_g);

    // ---- one-time: load Wr slice into smem (16 float4 per thread)
    #pragma unroll
    for (int u = 0; u < 16; u++) {
        int idx = u * THREADS + t;
        int kk2 = idx >> 4;
        int rem = idx & 15;
        int g = rem >> 2, jq = rem & 3;
        float4 v = __ldcg((const float4*)(Wr + (size_t)kk2 * G4_SZ + g * D_SZ + j0 + jq * 4));
        int jpA = jq * 2, jpB = jq * 2 + 1;
        float* dA = Ws + kk2 * WROW + jpA * 8 + (jpA >> 2) * 4 + g * 2;
        float* dB = Ws + kk2 * WROW + jpB * 8 + (jpB >> 2) * 4 + g * 2;
        dA[0] = v.x; dA[1] = v.y;
        dB[0] = v.z; dB[1] = v.w;
    }

    // barrier generation snapshot (stable until this CTA arrives)
    unsigned gen = 0;
    if (t == 0) gen = *((volatile unsigned*)&g_bar_gen);
    __syncthreads();

    // h staging map: 8 float4/thread/step
    const int h_row0 = t >> 3;          // 0..63, + pass*64
    const int h_bq   = (t & 7) * 4;

    for (int step = 0; step < T_STEPS; step++) {
        const float* hT_in  = g_hT[step & 1];
        float*       hT_out = g_hT[(step + 1) & 1];
        const float* intern_t = g_intern + (size_t)step * (B_SZ * G4_SZ);

        // ---- stage h: 8 coalesced LDG.128 (ldcg: dodge stale L1), then STS
        float4 hv[8];
        #pragma unroll
        for (int p = 0; p < 8; p++)
            hv[p] = __ldcg((const float4*)(hT_in + (size_t)(p * 64 + h_row0) * B_SZ + bm0 + h_bq));
        #pragma unroll
        for (int p = 0; p < 8; p++)
            *(float4*)(Hs + (p * 64 + h_row0) * HROW + h_bq) = hv[p];
        __syncthreads();

        // ---- mainloop: 64 k per split, 3 LDS.128 + 4 MOV + 16 FFMA2 each
        u64 acc[4][4];
        #pragma unroll
        for (int i = 0; i < 4; i++)
            #pragma unroll
            for (int g = 0; g < 4; g++) acc[i][g] = 0ull;

        #pragma unroll 8
        for (int m = 0; m < 64; m++) {
            int kc = m * 8 + ks;
            float4 hq = *(const float4*)(Hs + kc * HROW + bg * 4);
            ulonglong2 wA = *(const ulonglong2*)(Ws + kc * WROW + woff);
            ulonglong2 wB = *(const ulonglong2*)(Ws + kc * WROW + woff + 4);
            u64 hd[4] = {dup2(hq.x), dup2(hq.y), dup2(hq.z), dup2(hq.w)};
            u64 wd[4] = {wA.x, wA.y, wB.x, wB.y};
            #pragma unroll
            for (int i = 0; i < 4; i++)
                #pragma unroll
                for (int g = 0; g < 4; g++)
                    ffma2(acc[i][g], hd[i], wd[g]);
        }

        // ---- k-split reduction 8 -> 4 -> epilogue (red aliases Hs)
        __syncthreads();
        if (ks >= 4) {
            float* p = red + (ks - 4) * 2304 + slot * 36;
            #pragma unroll
            for (int i = 0; i < 4; i++) {
                *(ulonglong2*)(p + i * 8)     = make_ulonglong2(acc[i][0], acc[i][1]);
                *(ulonglong2*)(p + i * 8 + 4) = make_ulonglong2(acc[i][2], acc[i][3]);
            }
        }
        __syncthreads();
        if (ks < 4) {
            float* p = red + ks * 2304 + slot * 36;
            #pragma unroll
            for (int i = 0; i < 4; i++) {
                ulonglong2 v0 = *(ulonglong2*)(p + i * 8);
                ulonglong2 v1 = *(ulonglong2*)(p + i * 8 + 4);
                v0.x = add2(v0.x, acc[i][0]);
                v0.y = add2(v0.y, acc[i][1]);
                v1.x = add2(v1.x, acc[i][2]);
                v1.y = add2(v1.y, acc[i][3]);
                *(ulonglong2*)(p + i * 8)     = v0;
                *(ulonglong2*)(p + i * 8 + 4) = v1;
            }
        }
        __syncthreads();

        // ---- fused epilogue: one (b,j) cell per thread, c in register
        {
            float z[4];
            #pragma unroll
            for (int g = 0; g < 4; g++)
                z[g] = red[eoff + g * 2] + red[2304 + eoff + g * 2]
                     + red[4608 + eoff + g * 2] + red[6912 + eoff + g * 2];

            const float* it = intern_t + (size_t)b_g * G4_SZ + j_g;
            float zc = z[0] + __ldcg(it);
            float zi = z[1] + __ldcg(it + 512);
            float zf = z[2] + __ldcg(it + 1024);
            float zo = z[3] + __ldcg(it + 1536);

            zc = fminf(fmaxf(zc, -30.f), 30.f);
            float ec  = __expf(-2.f * zc);
            float cin = (1.f - ec) / (1.f + ec);
            float ig  = 1.f / (1.f + __expf(-zi));
            float fg  = 1.f / (1.f + __expf(-zf));
            float og  = 1.f / (1.f + __expf(-zo));

            float m    = __ldcg(iv + (size_t)step * B_SZ + b_g);
            float cnew = m * (c_reg * fg + cin * ig) + (1.f - m) * c_reg;
            c_reg = cnew;
            float ct = fminf(fmaxf(cnew, -30.f), 30.f);
            float e2 = __expf(-2.f * ct);
            float y  = m * (og * (1.f - e2) / (1.f + e2));

            size_t o = (size_t)step * (B_SZ * D_SZ) + (size_t)b_g * D_SZ + j_g;
            Y[o] = y;
            C[o] = cnew;
            if (step == T_STEPS - 1) d_fin[(size_t)b_g * D_SZ + j_g] = cnew;
            ybuf[b_l * 17 + jl] = y;
        }
        __syncthreads();

        // ---- write transposed h for next step (coalesced in b)
        {
            int jl2 = t >> 5;
            int b2  = t & 31;
            hT_out[(size_t)(j0 + jl2) * B_SZ + bm0 + b2] = ybuf[b2 * 17 + jl2];
        }

        // ---- grid-wide barrier (all 128 CTAs co-resident: 1 CTA/SM)
        __threadfence();
        __syncthreads();
        if (t == 0) {
            unsigned old = atomicAdd(&g_bar_cnt, 1);
            if (old == gridDim.x - 1) {
                g_bar_cnt = 0;
                __threadfence();
                atomicAdd(&g_bar_gen, 1);
            } else {
                while (*((volatile unsigned*)&g_bar_gen) == gen)
                    __nanosleep(64);
            }
            gen++;
        }
        __syncthreads();
    }
}

// ---------------------------------------------------------------------------
// Launch. Inputs: X, Wf, Wr, bf, i, h0, c0. Output: Y[T,B,D]|C[T,B,D]|d[B,D]
// ---------------------------------------------------------------------------
extern "C" void kernel_launch(void* const* d_in, const int* in_sizes, int n_in,
                              void* d_out, int out_size)
{
    (void)in_sizes; (void)n_in; (void)out_size;
    const float* X  = (const float*)d_in[0];
    const float* Wf = (const float*)d_in[1];
    const float* Wr = (const float*)d_in[2];
    const float* bf = (const float*)d_in[3];
    const float* iv = (const float*)d_in[4];
    const float* h0 = (const float*)d_in[5];
    const float* c0 = (const float*)d_in[6];

    float* out  = (float*)d_out;
    float* Y    = out;
    float* C    = out + (size_t)T_STEPS * B_SZ * D_SZ;
    float* dfin = C   + (size_t)T_STEPS * B_SZ * D_SZ;

    float* hT0; cudaGetSymbolAddress((void**)&hT0, g_hT);

    h0_transpose_kernel<<<256, 256>>>(h0);

    dim3 g1(G4_SZ / 128, (T_STEPS * B_SZ) / 128);  // (16, 512)
    gemm_intern_kernel<<<g1, 256>>>(X, Wf, bf);

    cudaFuncSetAttribute(lstm_persistent_kernel,
                         cudaFuncAttributeMaxDynamicSharedMemorySize,
                         SMEM_F * (int)sizeof(float));
    lstm_persistent_kernel<<<128, THREADS, SMEM_F * sizeof(float)>>>(
        hT0, c0, iv, Wr, Y, C, dfin);
}

// round 6
// speedup vs baseline: 1.5891x; 1.0701x over previous
#include <cuda_runtime.h>
#include <math.h>

#define T_STEPS 512
#define B_SZ    128
#define NI_SZ   512
#define D_SZ    512
#define G4_SZ   2048   // 4*D

typedef unsigned long long u64;

// Scratch (device globals: allocation-free rule workaround)
__device__ float g_intern[(size_t)T_STEPS * B_SZ * G4_SZ];
__device__ float g_hT[2][(size_t)D_SZ * B_SZ];   // transposed h mirror [k][b], ping-pong
__device__ unsigned g_bar_cnt4[4 * 32];          // per-group barrier (padded)
__device__ unsigned g_bar_gen4[4 * 32];

__device__ __forceinline__ void ffma2(u64 &d, u64 a, u64 b) {
    asm("fma.rn.f32x2 %0, %1, %2, %0;" : "+l"(d) : "l"(a), "l"(b));
}
__device__ __forceinline__ u64 dup2(float f) {
    u64 d; asm("mov.b64 %0, {%1, %1};" : "=l"(d) : "f"(f)); return d;
}
__device__ __forceinline__ u64 add2(u64 a, u64 b) {
    u64 d; asm("add.rn.f32x2 %0, %1, %2;" : "=l"(d) : "l"(a), "l"(b)); return d;
}
__device__ __forceinline__ float2 unpack2(u64 a) {
    float2 f; asm("mov.b64 {%0, %1}, %2;" : "=f"(f.x), "=f"(f.y) : "l"(a)); return f;
}

// ---------------------------------------------------------------------------
// h0 transpose: g_hT[0][k*128+b] = h0[b*512+k]
// ---------------------------------------------------------------------------
__global__ __launch_bounds__(256)
void h0_transpose_kernel(const float* __restrict__ h0)
{
    int idx = blockIdx.x * 256 + threadIdx.x;   // 65536 total
    int k = idx >> 7, b = idx & 127;
    g_hT[0][idx] = h0[b * D_SZ + k];
}

// ---------------------------------------------------------------------------
// Phase 1: intern = X@Wf + bf, 128x128x8 tile, FFMA2 (unchanged)
// ---------------------------------------------------------------------------
__global__ __launch_bounds__(256)
void gemm_intern_kernel(const float* __restrict__ X,
                        const float* __restrict__ Wf,
                        const float* __restrict__ bf)
{
    __shared__ __align__(16) float As[8][128];
    __shared__ __align__(16) float Bs[8][128];

    const int t  = threadIdx.x;
    const int tx = t & 15;
    const int ty = t >> 4;
    const int m0 = blockIdx.y * 128;
    const int n0 = blockIdx.x * 128;

    const int arow = t >> 1, acol = (t & 1) * 4;
    const int brow = t >> 5, bcol = (t & 31) * 4;

    const float* Aptr = X  + (size_t)(m0 + arow) * NI_SZ + acol;
    const float* Bptr = Wf + (size_t)brow * G4_SZ + n0 + bcol;

    u64 acc[8][4];
    #pragma unroll
    for (int i = 0; i < 8; i++)
        #pragma unroll
        for (int j = 0; j < 4; j++) acc[i][j] = 0ull;

    for (int k0 = 0; k0 < NI_SZ; k0 += 8) {
        float4 av = *(const float4*)(Aptr + k0);
        float4 bv = *(const float4*)(Bptr + (size_t)k0 * G4_SZ);
        __syncthreads();
        As[acol + 0][arow] = av.x;
        As[acol + 1][arow] = av.y;
        As[acol + 2][arow] = av.z;
        As[acol + 3][arow] = av.w;
        *(float4*)&Bs[brow][bcol] = bv;
        __syncthreads();
        #pragma unroll
        for (int k = 0; k < 8; k++) {
            float4 a0 = *(const float4*)&As[k][ty * 4];
            float4 a1 = *(const float4*)&As[k][64 + ty * 4];
            ulonglong2 bA = *(const ulonglong2*)&Bs[k][tx * 4];
            ulonglong2 bB = *(const ulonglong2*)&Bs[k][64 + tx * 4];
            u64 ad[8] = {dup2(a0.x), dup2(a0.y), dup2(a0.z), dup2(a0.w),
                         dup2(a1.x), dup2(a1.y), dup2(a1.z), dup2(a1.w)};
            #pragma unroll
            for (int i = 0; i < 8; i++) {
                ffma2(acc[i][0], ad[i], bA.x);
                ffma2(acc[i][1], ad[i], bA.y);
                ffma2(acc[i][2], ad[i], bB.x);
                ffma2(acc[i][3], ad[i], bB.y);
            }
        }
    }

    float4 bias0 = *(const float4*)&bf[n0 + tx * 4];
    float4 bias1 = *(const float4*)&bf[n0 + 64 + tx * 4];
    #pragma unroll
    for (int i = 0; i < 8; i++) {
        int m = m0 + (i < 4 ? ty * 4 + i : 64 + ty * 4 + (i - 4));
        float* out = g_intern + (size_t)m * G4_SZ + n0;
        float2 p0 = unpack2(acc[i][0]), p1 = unpack2(acc[i][1]);
        float2 p2 = unpack2(acc[i][2]), p3 = unpack2(acc[i][3]);
        float4 v0 = make_float4(p0.x + bias0.x, p0.y + bias0.y,
                                p1.x + bias0.z, p1.y + bias0.w);
        float4 v1 = make_float4(p2.x + bias1.x, p2.y + bias1.y,
                                p3.x + bias1.z, p3.y + bias1.w);
        *(float4*)(out + tx * 4)      = v0;
        *(float4*)(out + 64 + tx * 4) = v1;
    }
}

// ---------------------------------------------------------------------------
// Phase 2: persistent LSTM. 128 CTAs (1/SM), 512 threads = 16 warps.
// Warp = k-split (32 k each). Thread tile: 8b x 4j x 2g = 32 u64 j-packed
// accs. Per k: 2 LDS.128 (h) + 2 LDS.128 (w) + 8 MOV + 32 FFMA2 ->
// crossbar and FFMA2 floors both ~8.2K cyc, overlapped.
// Reduction: warps 8-15 store, warps 0-7 add in place, epilogue sums 8.
// Group barrier (32 CTAs sharing the b-block) + intern/iv prefetch.
// ---------------------------------------------------------------------------
#define THREADS 512
#define WROW 68                    // [k][8 jp x 4 g u64, skewed]
#define HROW 36                    // [k][32 b + pad]
#define WR_F (512 * WROW)          // 34816 floats
#define H_F  (512 * HROW)          // 18432 floats (red region: 17408 used)
#define SMEM_F (WR_F + H_F + 544)  // 53792 floats = 215168 bytes

__global__ __launch_bounds__(THREADS, 1)
void lstm_persistent_kernel(const float* __restrict__ hT0,
                            const float* __restrict__ c0,
                            const float* __restrict__ iv,
                            const float* __restrict__ Wr,
                            float* __restrict__ Y,
                            float* __restrict__ C,
                            float* __restrict__ d_fin)
{
    extern __shared__ __align__(16) float smem[];
    float* Ws   = smem;                 // Wr slice, persistent
    float* Hs   = smem + WR_F;          // h buffer (aliased by reduction)
    float* red  = Hs;                   // 8 arrays * 2176 floats
    float* ybuf = smem + WR_F + H_F;

    const int t    = threadIdx.x;
    const int bid  = blockIdx.x;        // 0..127
    const int j0   = (bid & 31) * 16;
    const int bm0  = (bid >> 5) * 32;
    const int grp  = bid >> 5;          // barrier group (32 CTAs)

    const int ks   = t >> 5;            // warp = k-split (32 k each)
    const int lane = t & 31;
    const int jq   = lane >> 3;         // j-quad (4 j each)
    const int gh   = (lane >> 2) & 1;   // gate-half
    const int bg   = lane & 3;          // b-group of 8
    const int jp0  = jq * 2;
    const int wboff = jp0 * 8 + (jp0 >> 2) * 4 + gh * 4;
    const int hboff = bg * 8;

    // epilogue cell (one per thread; c lives in a register)
    const int b_l = t >> 4, jl = t & 15;
    const int b_g = bm0 + b_l, j_g = j0 + jl;
    const int laneA = (jl >> 2) * 8 + (b_l >> 3);          // gh=0 source lane
    const int base_acc = (b_l & 7) * 4 + ((jl >> 1) & 1) * 2;
    const int offA = (laneA * 34 + base_acc) * 2 + (jl & 1);
    const int offB = offA + 272;                            // gh=1 (+4 lanes)
    float c_reg = __ldcg(c0 + (size_t)b_g * D_SZ + j_g);

    // ---- one-time: load Wr slice into smem (16 float4 per thread)
    #pragma unroll
    for (int u = 0; u < 16; u++) {
        int idx = u * THREADS + t;
        int kk2 = idx >> 4;
        int rem = idx & 15;
        int g = rem >> 2, jqs = rem & 3;
        float4 v = __ldcg((const float4*)(Wr + (size_t)kk2 * G4_SZ + g * D_SZ + j0 + jqs * 4));
        int jpA = jqs * 2, jpB = jqs * 2 + 1;
        float* dA = Ws + kk2 * WROW + jpA * 8 + (jpA >> 2) * 4 + g * 2;
        float* dB = Ws + kk2 * WROW + jpB * 8 + (jpB >> 2) * 4 + g * 2;
        dA[0] = v.x; dA[1] = v.y;
        dB[0] = v.z; dB[1] = v.w;
    }

    unsigned gen = 0;
    if (t == 0) gen = *((volatile unsigned*)&g_bar_gen4[grp * 32]);
    __syncthreads();

    // h staging map: 8 float4/thread/step (2 batches of 4 for reg pressure)
    const int h_row0 = t >> 3;          // 0..63
    const int h_bq   = (t & 7) * 4;

    // prefetch step 0 epilogue operands
    const float* itp = g_intern + (size_t)b_g * G4_SZ + j_g;
    float in0 = __ldcg(itp), in1 = __ldcg(itp + 512);
    float in2 = __ldcg(itp + 1024), in3 = __ldcg(itp + 1536);
    float mval = __ldcg(iv + b_g);

    for (int step = 0; step < T_STEPS; step++) {
        const float* hT_in  = g_hT[step & 1];
        float*       hT_out = g_hT[(step + 1) & 1];

        // ---- stage h (ldcg: dodge stale L1 on the ping-pong buffer)
        #pragma unroll
        for (int half = 0; half < 2; half++) {
            float4 hv[4];
            #pragma unroll
            for (int p = 0; p < 4; p++)
                hv[p] = __ldcg((const float4*)(hT_in +
                         (size_t)(half * 256 + p * 64 + h_row0) * B_SZ + bm0 + h_bq));
            #pragma unroll
            for (int p = 0; p < 4; p++)
                *(float4*)(Hs + (half * 256 + p * 64 + h_row0) * HROW + h_bq) = hv[p];
        }
        __syncthreads();

        // ---- mainloop: 32 k per warp-split
        u64 acc[8][4];
        #pragma unroll
        for (int i = 0; i < 8; i++)
            #pragma unroll
            for (int j = 0; j < 4; j++) acc[i][j] = 0ull;

        const float* hrow = Hs + (ks * 32) * HROW + hboff;
        const float* wrow = Ws + (ks * 32) * WROW + wboff;
        #pragma unroll 8
        for (int m = 0; m < 32; m++) {
            float4 h0v = *(const float4*)(hrow);
            float4 h1v = *(const float4*)(hrow + 4);
            ulonglong2 w0 = *(const ulonglong2*)(wrow);
            ulonglong2 w1 = *(const ulonglong2*)(wrow + 8);
            hrow += HROW; wrow += WROW;
            u64 wd[4] = {w0.x, w0.y, w1.x, w1.y};
            u64 hd[8] = {dup2(h0v.x), dup2(h0v.y), dup2(h0v.z), dup2(h0v.w),
                         dup2(h1v.x), dup2(h1v.y), dup2(h1v.z), dup2(h1v.w)};
            #pragma unroll
            for (int i = 0; i < 8; i++)
                #pragma unroll
                for (int j = 0; j < 4; j++)
                    ffma2(acc[i][j], hd[i], wd[j]);
        }

        // ---- reduction: 16 warp-copies -> 8 arrays (store high, add low)
        __syncthreads();
        if (ks >= 8) {
            float* p = red + (ks - 8) * 2176 + lane * 68;
            #pragma unroll
            for (int i = 0; i < 8; i++) {
                *(ulonglong2*)(p + i * 8)     = make_ulonglong2(acc[i][0], acc[i][1]);
                *(ulonglong2*)(p + i * 8 + 4) = make_ulonglong2(acc[i][2], acc[i][3]);
            }
        }
        __syncthreads();
        if (ks < 8) {
            float* p = red + ks * 2176 + lane * 68;
            #pragma unroll
            for (int i = 0; i < 8; i++) {
                ulonglong2 v0 = *(ulonglong2*)(p + i * 8);
                ulonglong2 v1 = *(ulonglong2*)(p + i * 8 + 4);
                v0.x = add2(v0.x, acc[i][0]);
                v0.y = add2(v0.y, acc[i][1]);
                v1.x = add2(v1.x, acc[i][2]);
                v1.y = add2(v1.y, acc[i][3]);
                *(ulonglong2*)(p + i * 8)     = v0;
                *(ulonglong2*)(p + i * 8 + 4) = v1;
            }
        }
        __syncthreads();

        // ---- fused epilogue
        {
            float z0 = 0.f, z1 = 0.f, z2 = 0.f, z3 = 0.f;
            #pragma unroll
            for (int wi = 0; wi < 8; wi++) {
                const float* p = red + wi * 2176;
                z0 += p[offA];
                z1 += p[offA + 2];
                z2 += p[offB];
                z3 += p[offB + 2];
            }

            float zc = z0 + in0;
            float zi = z1 + in1;
            float zf = z2 + in2;
            float zo = z3 + in3;

            zc = fminf(fmaxf(zc, -30.f), 30.f);
            float ec  = __expf(-2.f * zc);
            float cin = (1.f - ec) / (1.f + ec);
            float ig  = 1.f / (1.f + __expf(-zi));
            float fg  = 1.f / (1.f + __expf(-zf));
            float og  = 1.f / (1.f + __expf(-zo));

            float m    = mval;
            float cnew = m * (c_reg * fg + cin * ig) + (1.f - m) * c_reg;
            c_reg = cnew;
            float ct = fminf(fmaxf(cnew, -30.f), 30.f);
            float e2 = __expf(-2.f * ct);
            float y  = m * (og * (1.f - e2) / (1.f + e2));

            size_t o = (size_t)step * (B_SZ * D_SZ) + (size_t)b_g * D_SZ + j_g;
            Y[o] = y;
            C[o] = cnew;
            if (step == T_STEPS - 1) d_fin[(size_t)b_g * D_SZ + j_g] = cnew;
            ybuf[b_l * 17 + jl] = y;
        }
        __syncthreads();

        // ---- write transposed h for next step (coalesced in b)
        {
            int jl2 = t >> 5;
            int b2  = t & 31;
            hT_out[(size_t)(j0 + jl2) * B_SZ + bm0 + b2] = ybuf[b2 * 17 + jl2];
        }

        // ---- group barrier (32 CTAs sharing this b-block), with prefetch
        __threadfence();
        __syncthreads();
        unsigned old = 0;
        if (t == 0)
            old = atomicAdd(&g_bar_cnt4[grp * 32], 1);

        // prefetch next step's epilogue operands (overlaps barrier wait)
        if (step + 1 < T_STEPS) {
            const float* itn = g_intern + (size_t)(step + 1) * (B_SZ * G4_SZ)
                             + (size_t)b_g * G4_SZ + j_g;
            in0 = __ldcg(itn);
            in1 = __ldcg(itn + 512);
            in2 = __ldcg(itn + 1024);
            in3 = __ldcg(itn + 1536);
            mval = __ldcg(iv + (size_t)(step + 1) * B_SZ + b_g);
        }

        if (t == 0) {
            if (old == 31) {
                g_bar_cnt4[grp * 32] = 0;
                __threadfence();
                atomicAdd(&g_bar_gen4[grp * 32], 1);
            } else {
                while (*((volatile unsigned*)&g_bar_gen4[grp * 32]) == gen)
                    __nanosleep(32);
            }
            gen++;
        }
        __syncthreads();
    }
}

// ---------------------------------------------------------------------------
// Launch. Inputs: X, Wf, Wr, bf, i, h0, c0. Output: Y[T,B,D]|C[T,B,D]|d[B,D]
// ---------------------------------------------------------------------------
extern "C" void kernel_launch(void* const* d_in, const int* in_sizes, int n_in,
                              void* d_out, int out_size)
{
    (void)in_sizes; (void)n_in; (void)out_size;
    const float* X  = (const float*)d_in[0];
    const float* Wf = (const float*)d_in[1];
    const float* Wr = (const float*)d_in[2];
    const float* bf = (const float*)d_in[3];
    const float* iv = (const float*)d_in[4];
    const float* h0 = (const float*)d_in[5];
    const float* c0 = (const float*)d_in[6];

    float* out  = (float*)d_out;
    float* Y    = out;
    float* C    = out + (size_t)T_STEPS * B_SZ * D_SZ;
    float* dfin = C   + (size_t)T_STEPS * B_SZ * D_SZ;

    float* hT0; cudaGetSymbolAddress((void**)&hT0, g_hT);

    h0_transpose_kernel<<<256, 256>>>(h0);

    dim3 g1(G4_SZ / 128, (T_STEPS * B_SZ) / 128);  // (16, 512)
    gemm_intern_kernel<<<g1, 256>>>(X, Wf, bf);

    cudaFuncSetAttribute(lstm_persistent_kernel,
                         cudaFuncAttributeMaxDynamicSharedMemorySize,
                         SMEM_F * (int)sizeof(float));
    lstm_persistent_kernel<<<128, THREADS, SMEM_F * sizeof(float)>>>(
        hT0, c0, iv, Wr, Y, C, dfin);
}

// round 7
// speedup vs baseline: 1.6558x; 1.0419x over previous
#include <cuda_runtime.h>
#include <math.h>

#define T_STEPS 512
#define B_SZ    128
#define NI_SZ   512
#define D_SZ    512
#define G4_SZ   2048   // 4*D

typedef unsigned long long u64;

// Scratch (device globals: allocation-free rule workaround)
__device__ float g_intern[(size_t)T_STEPS * B_SZ * G4_SZ];
__device__ float g_hT[2][(size_t)D_SZ * B_SZ];   // transposed h mirror [k][b], ping-pong
__device__ unsigned g_flag[128 * 32];            // per-CTA produce flag (128B padded)

__device__ __forceinline__ void ffma2(u64 &d, u64 a, u64 b) {
    asm("fma.rn.f32x2 %0, %1, %2, %0;" : "+l"(d) : "l"(a), "l"(b));
}
__device__ __forceinline__ u64 dup2(float f) {
    u64 d; asm("mov.b64 %0, {%1, %1};" : "=l"(d) : "f"(f)); return d;
}
__device__ __forceinline__ u64 add2(u64 a, u64 b) {
    u64 d; asm("add.rn.f32x2 %0, %1, %2;" : "=l"(d) : "l"(a), "l"(b)); return d;
}
__device__ __forceinline__ float2 unpack2(u64 a) {
    float2 f; asm("mov.b64 {%0, %1}, %2;" : "=f"(f.x), "=f"(f.y) : "l"(a)); return f;
}
__device__ __forceinline__ unsigned ld_acq(const unsigned* p) {
    unsigned v;
    asm volatile("ld.acquire.gpu.global.u32 %0, [%1];" : "=r"(v) : "l"(p) : "memory");
    return v;
}

// ---------------------------------------------------------------------------
// h0 transpose: g_hT[0][k*128+b] = h0[b*512+k]
// ---------------------------------------------------------------------------
__global__ __launch_bounds__(256)
void h0_transpose_kernel(const float* __restrict__ h0)
{
    int idx = blockIdx.x * 256 + threadIdx.x;   // 65536 total
    int k = idx >> 7, b = idx & 127;
    g_hT[0][idx] = h0[b * D_SZ + k];
}

// ---------------------------------------------------------------------------
// Phase 1: intern = X@Wf + bf, 128x128x8 tile, FFMA2 (at roofline; unchanged)
// ---------------------------------------------------------------------------
__global__ __launch_bounds__(256)
void gemm_intern_kernel(const float* __restrict__ X,
                        const float* __restrict__ Wf,
                        const float* __restrict__ bf)
{
    __shared__ __align__(16) float As[8][128];
    __shared__ __align__(16) float Bs[8][128];

    const int t  = threadIdx.x;
    const int tx = t & 15;
    const int ty = t >> 4;
    const int m0 = blockIdx.y * 128;
    const int n0 = blockIdx.x * 128;

    const int arow = t >> 1, acol = (t & 1) * 4;
    const int brow = t >> 5, bcol = (t & 31) * 4;

    const float* Aptr = X  + (size_t)(m0 + arow) * NI_SZ + acol;
    const float* Bptr = Wf + (size_t)brow * G4_SZ + n0 + bcol;

    u64 acc[8][4];
    #pragma unroll
    for (int i = 0; i < 8; i++)
        #pragma unroll
        for (int j = 0; j < 4; j++) acc[i][j] = 0ull;

    for (int k0 = 0; k0 < NI_SZ; k0 += 8) {
        float4 av = *(const float4*)(Aptr + k0);
        float4 bv = *(const float4*)(Bptr + (size_t)k0 * G4_SZ);
        __syncthreads();
        As[acol + 0][arow] = av.x;
        As[acol + 1][arow] = av.y;
        As[acol + 2][arow] = av.z;
        As[acol + 3][arow] = av.w;
        *(float4*)&Bs[brow][bcol] = bv;
        __syncthreads();
        #pragma unroll
        for (int k = 0; k < 8; k++) {
            float4 a0 = *(const float4*)&As[k][ty * 4];
            float4 a1 = *(const float4*)&As[k][64 + ty * 4];
            ulonglong2 bA = *(const ulonglong2*)&Bs[k][tx * 4];
            ulonglong2 bB = *(const ulonglong2*)&Bs[k][64 + tx * 4];
            u64 ad[8] = {dup2(a0.x), dup2(a0.y), dup2(a0.z), dup2(a0.w),
                         dup2(a1.x), dup2(a1.y), dup2(a1.z), dup2(a1.w)};
            #pragma unroll
            for (int i = 0; i < 8; i++) {
                ffma2(acc[i][0], ad[i], bA.x);
                ffma2(acc[i][1], ad[i], bA.y);
                ffma2(acc[i][2], ad[i], bB.x);
                ffma2(acc[i][3], ad[i], bB.y);
            }
        }
    }

    float4 bias0 = *(const float4*)&bf[n0 + tx * 4];
    float4 bias1 = *(const float4*)&bf[n0 + 64 + tx * 4];
    #pragma unroll
    for (int i = 0; i < 8; i++) {
        int m = m0 + (i < 4 ? ty * 4 + i : 64 + ty * 4 + (i - 4));
        float* out = g_intern + (size_t)m * G4_SZ + n0;
        float2 p0 = unpack2(acc[i][0]), p1 = unpack2(acc[i][1]);
        float2 p2 = unpack2(acc[i][2]), p3 = unpack2(acc[i][3]);
        float4 v0 = make_float4(p0.x + bias0.x, p0.y + bias0.y,
                                p1.x + bias0.z, p1.y + bias0.w);
        float4 v1 = make_float4(p2.x + bias1.x, p2.y + bias1.y,
                                p3.x + bias1.z, p3.y + bias1.w);
        *(float4*)(out + tx * 4)      = v0;
        *(float4*)(out + 64 + tx * 4) = v1;
    }
}

// ---------------------------------------------------------------------------
// Phase 2: persistent LSTM, flag-based producer/consumer sync (NO group
// barrier). 128 CTAs (1/SM), 512 threads = 16 warps = 16 k-splits.
// Consumer warp ks depends on exactly 2 producer CTAs (j-slices 2ks, 2ks+1):
// acquire-poll their flags, stage own 32 h rows (warp-local), mainloop.
// CTA-wide syncs only around the fold + epilogue.
// ---------------------------------------------------------------------------
#define THREADS 512
#define WROW 68                    // [k][8 jp x 4 g u64, skewed]
#define HROW 36                    // [k][32 b + pad]
#define WR_F (512 * WROW)          // 34816 floats
#define H_F  (512 * HROW)          // 18432 floats (red region: 17408 used)
#define SMEM_F (WR_F + H_F + 544)  // 53792 floats = 215168 bytes

__global__ __launch_bounds__(THREADS, 1)
void lstm_persistent_kernel(const float* __restrict__ hT0,
                            const float* __restrict__ c0,
                            const float* __restrict__ iv,
                            const float* __restrict__ Wr,
                            float* __restrict__ Y,
                            float* __restrict__ C,
                            float* __restrict__ d_fin)
{
    extern __shared__ __align__(16) float smem[];
    float* Ws   = smem;                 // Wr slice, persistent
    float* Hs   = smem + WR_F;          // h buffer (aliased by reduction)
    float* red  = Hs;                   // 8 arrays * 2176 floats
    float* ybuf = smem + WR_F + H_F;

    const int t    = threadIdx.x;
    const int bid  = blockIdx.x;        // 0..127
    const int j0   = (bid & 31) * 16;
    const int bm0  = (bid >> 5) * 32;
    const int grp  = bid >> 5;

    const int ks   = t >> 5;            // warp = k-split (32 k each)
    const int lane = t & 31;
    const int jq   = lane >> 3;         // j-quad
    const int gh   = (lane >> 2) & 1;   // gate-half
    const int bg   = lane & 3;          // b-group of 8
    const int jp0  = jq * 2;
    const int wboff = jp0 * 8 + (jp0 >> 2) * 4 + gh * 4;
    const int hboff = bg * 8;

    // epilogue cell (one per thread; c lives in a register)
    const int b_l = t >> 4, jl = t & 15;
    const int b_g = bm0 + b_l, j_g = j0 + jl;
    const int laneA = (jl >> 2) * 8 + (b_l >> 3);
    const int base_acc = (b_l & 7) * 4 + ((jl >> 1) & 1) * 2;
    const int offA = (laneA * 34 + base_acc) * 2 + (jl & 1);
    const int offB = offA + 272;
    float c_reg = __ldcg(c0 + (size_t)b_g * D_SZ + j_g);

    // ---- flags: own base + the 2 producers this warp depends on
    const unsigned fbase = g_flag[bid * 32];
    const unsigned* fp0 = &g_flag[(grp * 32 + 2 * ks) * 32];
    const unsigned* fp1 = &g_flag[(grp * 32 + 2 * ks + 1) * 32];

    // ---- one-time: load Wr slice into smem (16 float4 per thread)
    #pragma unroll
    for (int u = 0; u < 16; u++) {
        int idx = u * THREADS + t;
        int kk2 = idx >> 4;
        int rem = idx & 15;
        int g = rem >> 2, jqs = rem & 3;
        float4 v = __ldcg((const float4*)(Wr + (size_t)kk2 * G4_SZ + g * D_SZ + j0 + jqs * 4));
        int jpA = jqs * 2, jpB = jqs * 2 + 1;
        float* dA = Ws + kk2 * WROW + jpA * 8 + (jpA >> 2) * 4 + g * 2;
        float* dB = Ws + kk2 * WROW + jpB * 8 + (jpB >> 2) * 4 + g * 2;
        dA[0] = v.x; dA[1] = v.y;
        dB[0] = v.z; dB[1] = v.w;
    }
    __syncthreads();

    // warp-local h staging map: warp ks stages rows [32ks, 32ks+32)
    const int s_r0 = ks * 32 + (lane >> 3);   // + 4 per u
    const int s_bq = (lane & 7) * 4;

    // prefetch step 0 epilogue operands
    const float* itp = g_intern + (size_t)b_g * G4_SZ + j_g;
    float in0 = __ldcg(itp), in1 = __ldcg(itp + 512);
    float in2 = __ldcg(itp + 1024), in3 = __ldcg(itp + 1536);
    float mval = __ldcg(iv + b_g);

    for (int step = 0; step < T_STEPS; step++) {
        const float* hT_in  = g_hT[step & 1];
        float*       hT_out = g_hT[(step + 1) & 1];

        // ---- per-warp wait: my 2 producers must have published h(step)
        if (step > 0) {
            unsigned need = fbase + (unsigned)step;
            while ((int)(ld_acq(fp0) - need) < 0) __nanosleep(20);
            while ((int)(ld_acq(fp1) - need) < 0) __nanosleep(20);
        }

        // ---- stage own 32 rows (warp-local; ldcg dodges stale L1)
        {
            float4 hv[8];
            #pragma unroll
            for (int u = 0; u < 8; u++)
                hv[u] = __ldcg((const float4*)(hT_in +
                          (size_t)(s_r0 + u * 4) * B_SZ + bm0 + s_bq));
            #pragma unroll
            for (int u = 0; u < 8; u++)
                *(float4*)(Hs + (s_r0 + u * 4) * HROW + s_bq) = hv[u];
        }
        __syncwarp();

        // ---- mainloop: 32 k (own rows only)
        u64 acc[8][4];
        #pragma unroll
        for (int i = 0; i < 8; i++)
            #pragma unroll
            for (int j = 0; j < 4; j++) acc[i][j] = 0ull;

        const float* hrow = Hs + (ks * 32) * HROW + hboff;
        const float* wrow = Ws + (ks * 32) * WROW + wboff;
        #pragma unroll 8
        for (int m = 0; m < 32; m++) {
            float4 h0v = *(const float4*)(hrow);
            float4 h1v = *(const float4*)(hrow + 4);
            ulonglong2 w0 = *(const ulonglong2*)(wrow);
            ulonglong2 w1 = *(const ulonglong2*)(wrow + 8);
            hrow += HROW; wrow += WROW;
            u64 wd[4] = {w0.x, w0.y, w1.x, w1.y};
            u64 hd[8] = {dup2(h0v.x), dup2(h0v.y), dup2(h0v.z), dup2(h0v.w),
                         dup2(h1v.x), dup2(h1v.y), dup2(h1v.z), dup2(h1v.w)};
            #pragma unroll
            for (int i = 0; i < 8; i++)
                #pragma unroll
                for (int j = 0; j < 4; j++)
                    ffma2(acc[i][j], hd[i], wd[j]);
        }

        // ---- fold: 16 warp-copies -> 8 arrays (store high, add low)
        __syncthreads();
        if (ks >= 8) {
            float* p = red + (ks - 8) * 2176 + lane * 68;
            #pragma unroll
            for (int i = 0; i < 8; i++) {
                *(ulonglong2*)(p + i * 8)     = make_ulonglong2(acc[i][0], acc[i][1]);
                *(ulonglong2*)(p + i * 8 + 4) = make_ulonglong2(acc[i][2], acc[i][3]);
            }
        }
        __syncthreads();
        if (ks < 8) {
            float* p = red + ks * 2176 + lane * 68;
            #pragma unroll
            for (int i = 0; i < 8; i++) {
                ulonglong2 v0 = *(ulonglong2*)(p + i * 8);
                ulonglong2 v1 = *(ulonglong2*)(p + i * 8 + 4);
                v0.x = add2(v0.x, acc[i][0]);
                v0.y = add2(v0.y, acc[i][1]);
                v1.x = add2(v1.x, acc[i][2]);
                v1.y = add2(v1.y, acc[i][3]);
                *(ulonglong2*)(p + i * 8)     = v0;
                *(ulonglong2*)(p + i * 8 + 4) = v1;
            }
        }
        __syncthreads();

        // ---- fused epilogue (smem only; gmem writes deferred)
        float y_out;
        {
            float z0 = 0.f, z1 = 0.f, z2 = 0.f, z3 = 0.f;
            #pragma unroll
            for (int wi = 0; wi < 8; wi++) {
                const float* p = red + wi * 2176;
                z0 += p[offA];
                z1 += p[offA + 2];
                z2 += p[offB];
                z3 += p[offB + 2];
            }

            float zc = z0 + in0;
            float zi = z1 + in1;
            float zf = z2 + in2;
            float zo = z3 + in3;

            zc = fminf(fmaxf(zc, -30.f), 30.f);
            float ec  = __expf(-2.f * zc);
            float cin = (1.f - ec) / (1.f + ec);
            float ig  = 1.f / (1.f + __expf(-zi));
            float fg  = 1.f / (1.f + __expf(-zf));
            float og  = 1.f / (1.f + __expf(-zo));

            float m    = mval;
            float cnew = m * (c_reg * fg + cin * ig) + (1.f - m) * c_reg;
            c_reg = cnew;
            float ct = fminf(fmaxf(cnew, -30.f), 30.f);
            float e2 = __expf(-2.f * ct);
            y_out = m * (og * (1.f - e2) / (1.f + e2));

            ybuf[b_l * 17 + jl] = y_out;
        }
        __syncthreads();

        // ---- publish h(step+1): transposed write + release flag
        if (step + 1 < T_STEPS) {
            int jl2 = t >> 5;
            int b2  = t & 31;
            hT_out[(size_t)(j0 + jl2) * B_SZ + bm0 + b2] = ybuf[b2 * 17 + jl2];
        }
        __syncthreads();
        if (step + 1 < T_STEPS && t == 0) {
            __threadfence();    // cumulative: covers all threads' hT STGs
            atomicExch(&g_flag[bid * 32], fbase + (unsigned)step + 1);
        }

        // ---- deferred gmem writes (after flag: off the critical path)
        {
            size_t o = (size_t)step * (B_SZ * D_SZ) + (size_t)b_g * D_SZ + j_g;
            Y[o] = y_out;
            C[o] = c_reg;
            if (step == T_STEPS - 1) d_fin[(size_t)b_g * D_SZ + j_g] = c_reg;
        }

        // ---- prefetch next step's epilogue operands
        if (step + 1 < T_STEPS) {
            const float* itn = g_intern + (size_t)(step + 1) * (B_SZ * G4_SZ)
                             + (size_t)b_g * G4_SZ + j_g;
            in0 = __ldcg(itn);
            in1 = __ldcg(itn + 512);
            in2 = __ldcg(itn + 1024);
            in3 = __ldcg(itn + 1536);
            mval = __ldcg(iv + (size_t)(step + 1) * B_SZ + b_g);
        }
    }
}

// ---------------------------------------------------------------------------
// Launch. Inputs: X, Wf, Wr, bf, i, h0, c0. Output: Y[T,B,D]|C[T,B,D]|d[B,D]
// ---------------------------------------------------------------------------
extern "C" void kernel_launch(void* const* d_in, const int* in_sizes, int n_in,
                              void* d_out, int out_size)
{
    (void)in_sizes; (void)n_in; (void)out_size;
    const float* X  = (const float*)d_in[0];
    const float* Wf = (const float*)d_in[1];
    const float* Wr = (const float*)d_in[2];
    const float* bf = (const float*)d_in[3];
    const float* iv = (const float*)d_in[4];
    const float* h0 = (const float*)d_in[5];
    const float* c0 = (const float*)d_in[6];

    float* out  = (float*)d_out;
    float* Y    = out;
    float* C    = out + (size_t)T_STEPS * B_SZ * D_SZ;
    float* dfin = C   + (size_t)T_STEPS * B_SZ * D_SZ;

    float* hT0; cudaGetSymbolAddress((void**)&hT0, g_hT);

    h0_transpose_kernel<<<256, 256>>>(h0);

    dim3 g1(G4_SZ / 128, (T_STEPS * B_SZ) / 128);  // (16, 512)
    gemm_intern_kernel<<<g1, 256>>>(X, Wf, bf);

    cudaFuncSetAttribute(lstm_persistent_kernel,
                         cudaFuncAttributeMaxDynamicSharedMemorySize,
                         SMEM_F * (int)sizeof(float));
    lstm_persistent_kernel<<<128, THREADS, SMEM_F * sizeof(float)>>>(
        hT0, c0, iv, Wr, Y, C, dfin);
}

// round 8
// speedup vs baseline: 1.6643x; 1.0052x over previous
#include <cuda_runtime.h>
#include <math.h>

#define T_STEPS 512
#define B_SZ    128
#define NI_SZ   512
#define D_SZ    512
#define G4_SZ   2048   // 4*D

typedef unsigned long long u64;

// Scratch (device globals: allocation-free rule workaround)
__device__ float g_intern[(size_t)T_STEPS * B_SZ * G4_SZ];
__device__ float g_hT[2][(size_t)D_SZ * B_SZ];   // transposed h mirror [k][b], ping-pong
__device__ unsigned g_flag[128 * 32];            // per-CTA produce flag (128B padded)

__device__ __forceinline__ void ffma2(u64 &d, u64 a, u64 b) {
    asm("fma.rn.f32x2 %0, %1, %2, %0;" : "+l"(d) : "l"(a), "l"(b));
}
__device__ __forceinline__ u64 dup2(float f) {
    u64 d; asm("mov.b64 %0, {%1, %1};" : "=l"(d) : "f"(f)); return d;
}
__device__ __forceinline__ u64 add2(u64 a, u64 b) {
    u64 d; asm("add.rn.f32x2 %0, %1, %2;" : "=l"(d) : "l"(a), "l"(b)); return d;
}
__device__ __forceinline__ float2 unpack2(u64 a) {
    float2 f; asm("mov.b64 {%0, %1}, %2;" : "=f"(f.x), "=f"(f.y) : "l"(a)); return f;
}
__device__ __forceinline__ unsigned ld_acq(const unsigned* p) {
    unsigned v;
    asm volatile("ld.acquire.gpu.global.u32 %0, [%1];" : "=r"(v) : "l"(p) : "memory");
    return v;
}
__device__ __forceinline__ void st_release_exch(unsigned* p, unsigned v) {
    unsigned tmp;
    asm volatile("atom.release.gpu.global.exch.b32 %0, [%1], %2;"
                 : "=r"(tmp) : "l"(p), "r"(v) : "memory");
}

// ---------------------------------------------------------------------------
// h0 transpose: g_hT[0][k*128+b] = h0[b*512+k]
// ---------------------------------------------------------------------------
__global__ __launch_bounds__(256)
void h0_transpose_kernel(const float* __restrict__ h0)
{
    int idx = blockIdx.x * 256 + threadIdx.x;   // 65536 total
    int k = idx >> 7, b = idx & 127;
    g_hT[0][idx] = h0[b * D_SZ + k];
}

// ---------------------------------------------------------------------------
// Phase 1: intern = X@Wf + bf, 128x128x8 tile, FFMA2 (unchanged)
// ---------------------------------------------------------------------------
__global__ __launch_bounds__(256)
void gemm_intern_kernel(const float* __restrict__ X,
                        const float* __restrict__ Wf,
                        const float* __restrict__ bf)
{
    __shared__ __align__(16) float As[8][128];
    __shared__ __align__(16) float Bs[8][128];

    const int t  = threadIdx.x;
    const int tx = t & 15;
    const int ty = t >> 4;
    const int m0 = blockIdx.y * 128;
    const int n0 = blockIdx.x * 128;

    const int arow = t >> 1, acol = (t & 1) * 4;
    const int brow = t >> 5, bcol = (t & 31) * 4;

    const float* Aptr = X  + (size_t)(m0 + arow) * NI_SZ + acol;
    const float* Bptr = Wf + (size_t)brow * G4_SZ + n0 + bcol;

    u64 acc[8][4];
    #pragma unroll
    for (int i = 0; i < 8; i++)
        #pragma unroll
        for (int j = 0; j < 4; j++) acc[i][j] = 0ull;

    for (int k0 = 0; k0 < NI_SZ; k0 += 8) {
        float4 av = *(const float4*)(Aptr + k0);
        float4 bv = *(const float4*)(Bptr + (size_t)k0 * G4_SZ);
        __syncthreads();
        As[acol + 0][arow] = av.x;
        As[acol + 1][arow] = av.y;
        As[acol + 2][arow] = av.z;
        As[acol + 3][arow] = av.w;
        *(float4*)&Bs[brow][bcol] = bv;
        __syncthreads();
        #pragma unroll
        for (int k = 0; k < 8; k++) {
            float4 a0 = *(const float4*)&As[k][ty * 4];
            float4 a1 = *(const float4*)&As[k][64 + ty * 4];
            ulonglong2 bA = *(const ulonglong2*)&Bs[k][tx * 4];
            ulonglong2 bB = *(const ulonglong2*)&Bs[k][64 + tx * 4];
            u64 ad[8] = {dup2(a0.x), dup2(a0.y), dup2(a0.z), dup2(a0.w),
                         dup2(a1.x), dup2(a1.y), dup2(a1.z), dup2(a1.w)};
            #pragma unroll
            for (int i = 0; i < 8; i++) {
                ffma2(acc[i][0], ad[i], bA.x);
                ffma2(acc[i][1], ad[i], bA.y);
                ffma2(acc[i][2], ad[i], bB.x);
                ffma2(acc[i][3], ad[i], bB.y);
            }
        }
    }

    float4 bias0 = *(const float4*)&bf[n0 + tx * 4];
    float4 bias1 = *(const float4*)&bf[n0 + 64 + tx * 4];
    #pragma unroll
    for (int i = 0; i < 8; i++) {
        int m = m0 + (i < 4 ? ty * 4 + i : 64 + ty * 4 + (i - 4));
        float* out = g_intern + (size_t)m * G4_SZ + n0;
        float2 p0 = unpack2(acc[i][0]), p1 = unpack2(acc[i][1]);
        float2 p2 = unpack2(acc[i][2]), p3 = unpack2(acc[i][3]);
        float4 v0 = make_float4(p0.x + bias0.x, p0.y + bias0.y,
                                p1.x + bias0.z, p1.y + bias0.w);
        float4 v1 = make_float4(p2.x + bias1.x, p2.y + bias1.y,
                                p3.x + bias1.z, p3.y + bias1.w);
        *(float4*)(out + tx * 4)      = v0;
        *(float4*)(out + 64 + tx * 4) = v1;
    }
}

// ---------------------------------------------------------------------------
// Phase 2: persistent LSTM, flag-based producer/consumer sync.
// 128 CTAs (1/SM), 512 threads = 16 warps = 16 k-splits.
// This round: direct scattered hT publish (no ybuf, -2 syncs), release-atomic
// flag, vectorized epilogue (LDS.128 + packed add2).
// ---------------------------------------------------------------------------
#define THREADS 512
#define WROW 68                    // [k][8 jp x 4 g u64, skewed]
#define HROW 36                    // [k][32 b + pad]
#define WR_F (512 * WROW)          // 34816 floats
#define H_F  (512 * HROW)          // 18432 floats (red region: 17408 used)
#define SMEM_F (WR_F + H_F)        // 53248 floats = 212992 bytes

__global__ __launch_bounds__(THREADS, 1)
void lstm_persistent_kernel(const float* __restrict__ hT0,
                            const float* __restrict__ c0,
                            const float* __restrict__ iv,
                            const float* __restrict__ Wr,
                            float* __restrict__ Y,
                            float* __restrict__ C,
                            float* __restrict__ d_fin)
{
    extern __shared__ __align__(16) float smem[];
    float* Ws   = smem;                 // Wr slice, persistent
    float* Hs   = smem + WR_F;          // h buffer (aliased by reduction)
    float* red  = Hs;                   // 8 arrays * 2176 floats

    const int t    = threadIdx.x;
    const int bid  = blockIdx.x;        // 0..127
    const int j0   = (bid & 31) * 16;
    const int bm0  = (bid >> 5) * 32;
    const int grp  = bid >> 5;

    const int ks   = t >> 5;            // warp = k-split (32 k each)
    const int lane = t & 31;
    const int jq   = lane >> 3;         // j-quad
    const int gh   = (lane >> 2) & 1;   // gate-half
    const int bg   = lane & 3;          // b-group of 8
    const int jp0  = jq * 2;
    const int wboff = jp0 * 8 + (jp0 >> 2) * 4 + gh * 4;
    const int hboff = bg * 8;

    // epilogue cell (one per thread; c lives in a register)
    const int b_l = t >> 4, jl = t & 15;
    const int b_g = bm0 + b_l, j_g = j0 + jl;
    const int laneA = (jl >> 2) * 8 + (b_l >> 3);
    // 16B-aligned float4 base holding (gate0 even/odd, gate1 even/odd) for gh=0
    const int eoff4 = laneA * 68 + (b_l & 7) * 8 + ((jl >> 1) & 1) * 4;
    const int p_odd = jl & 1;
    float c_reg = __ldcg(c0 + (size_t)b_g * D_SZ + j_g);

    // ---- flags: own base + the 2 producers this warp depends on
    const unsigned fbase = g_flag[bid * 32];
    const unsigned* fp0 = &g_flag[(grp * 32 + 2 * ks) * 32];
    const unsigned* fp1 = &g_flag[(grp * 32 + 2 * ks + 1) * 32];

    // ---- one-time: load Wr slice into smem (16 float4 per thread)
    #pragma unroll
    for (int u = 0; u < 16; u++) {
        int idx = u * THREADS + t;
        int kk2 = idx >> 4;
        int rem = idx & 15;
        int g = rem >> 2, jqs = rem & 3;
        float4 v = __ldcg((const float4*)(Wr + (size_t)kk2 * G4_SZ + g * D_SZ + j0 + jqs * 4));
        int jpA = jqs * 2, jpB = jqs * 2 + 1;
        float* dA = Ws + kk2 * WROW + jpA * 8 + (jpA >> 2) * 4 + g * 2;
        float* dB = Ws + kk2 * WROW + jpB * 8 + (jpB >> 2) * 4 + g * 2;
        dA[0] = v.x; dA[1] = v.y;
        dB[0] = v.z; dB[1] = v.w;
    }
    __syncthreads();

    // warp-local h staging map: warp ks stages rows [32ks, 32ks+32)
    const int s_r0 = ks * 32 + (lane >> 3);   // + 4 per u
    const int s_bq = (lane & 7) * 4;

    // prefetch step 0 epilogue operands
    const float* itp = g_intern + (size_t)b_g * G4_SZ + j_g;
    float in0 = __ldcg(itp), in1 = __ldcg(itp + 512);
    float in2 = __ldcg(itp + 1024), in3 = __ldcg(itp + 1536);
    float mval = __ldcg(iv + b_g);

    for (int step = 0; step < T_STEPS; step++) {
        const float* hT_in  = g_hT[step & 1];
        float*       hT_out = g_hT[(step + 1) & 1];

        // ---- per-warp wait: my 2 producers must have published h(step)
        if (step > 0) {
            unsigned need = fbase + (unsigned)step;
            if ((int)(ld_acq(fp0) - need) < 0)
                do { __nanosleep(20); } while ((int)(ld_acq(fp0) - need) < 0);
            if ((int)(ld_acq(fp1) - need) < 0)
                do { __nanosleep(20); } while ((int)(ld_acq(fp1) - need) < 0);
        }

        // ---- stage own 32 rows (warp-local; ldcg dodges stale L1)
        {
            float4 hv[8];
            #pragma unroll
            for (int u = 0; u < 8; u++)
                hv[u] = __ldcg((const float4*)(hT_in +
                          (size_t)(s_r0 + u * 4) * B_SZ + bm0 + s_bq));
            #pragma unroll
            for (int u = 0; u < 8; u++)
                *(float4*)(Hs + (s_r0 + u * 4) * HROW + s_bq) = hv[u];
        }
        __syncwarp();

        // ---- mainloop: 32 k (own rows only)
        u64 acc[8][4];
        #pragma unroll
        for (int i = 0; i < 8; i++)
            #pragma unroll
            for (int j = 0; j < 4; j++) acc[i][j] = 0ull;

        const float* hrow = Hs + (ks * 32) * HROW + hboff;
        const float* wrow = Ws + (ks * 32) * WROW + wboff;
        #pragma unroll 8
        for (int m = 0; m < 32; m++) {
            float4 h0v = *(const float4*)(hrow);
            float4 h1v = *(const float4*)(hrow + 4);
            ulonglong2 w0 = *(const ulonglong2*)(wrow);
            ulonglong2 w1 = *(const ulonglong2*)(wrow + 8);
            hrow += HROW; wrow += WROW;
            u64 wd[4] = {w0.x, w0.y, w1.x, w1.y};
            u64 hd[8] = {dup2(h0v.x), dup2(h0v.y), dup2(h0v.z), dup2(h0v.w),
                         dup2(h1v.x), dup2(h1v.y), dup2(h1v.z), dup2(h1v.w)};
            #pragma unroll
            for (int i = 0; i < 8; i++)
                #pragma unroll
                for (int j = 0; j < 4; j++)
                    ffma2(acc[i][j], hd[i], wd[j]);
        }

        // ---- fold: 16 warp-copies -> 8 arrays (store high, add low)
        __syncthreads();
        if (ks >= 8) {
            float* p = red + (ks - 8) * 2176 + lane * 68;
            #pragma unroll
            for (int i = 0; i < 8; i++) {
                *(ulonglong2*)(p + i * 8)     = make_ulonglong2(acc[i][0], acc[i][1]);
                *(ulonglong2*)(p + i * 8 + 4) = make_ulonglong2(acc[i][2], acc[i][3]);
            }
        }
        __syncthreads();
        if (ks < 8) {
            float* p = red + ks * 2176 + lane * 68;
            #pragma unroll
            for (int i = 0; i < 8; i++) {
                ulonglong2 v0 = *(ulonglong2*)(p + i * 8);
                ulonglong2 v1 = *(ulonglong2*)(p + i * 8 + 4);
                v0.x = add2(v0.x, acc[i][0]);
                v0.y = add2(v0.y, acc[i][1]);
                v1.x = add2(v1.x, acc[i][2]);
                v1.y = add2(v1.y, acc[i][3]);
                *(ulonglong2*)(p + i * 8)     = v0;
                *(ulonglong2*)(p + i * 8 + 4) = v1;
            }
        }
        __syncthreads();

        // ---- fused epilogue: vectorized reads + packed add2 trees
        float y_out;
        {
            u64 sA0 = 0ull, sA1 = 0ull, sB0 = 0ull, sB1 = 0ull;
            #pragma unroll
            for (int wi = 0; wi < 8; wi++) {
                const float* p = red + wi * 2176;
                ulonglong2 vA = *(const ulonglong2*)(p + eoff4);        // gates 0,1
                ulonglong2 vB = *(const ulonglong2*)(p + eoff4 + 272);  // gates 2,3
                sA0 = add2(sA0, vA.x);
                sA1 = add2(sA1, vA.y);
                sB0 = add2(sB0, vB.x);
                sB1 = add2(sB1, vB.y);
            }
            float2 a0 = unpack2(sA0), a1 = unpack2(sA1);
            float2 b0 = unpack2(sB0), b1 = unpack2(sB1);
            float z0 = p_odd ? a0.y : a0.x;
            float z1 = p_odd ? a1.y : a1.x;
            float z2 = p_odd ? b0.y : b0.x;
            float z3 = p_odd ? b1.y : b1.x;

            float zc = z0 + in0;
            float zi = z1 + in1;
            float zf = z2 + in2;
            float zo = z3 + in3;

            zc = fminf(fmaxf(zc, -30.f), 30.f);
            float ec  = __expf(-2.f * zc);
            float cin = (1.f - ec) / (1.f + ec);
            float ig  = 1.f / (1.f + __expf(-zi));
            float fg  = 1.f / (1.f + __expf(-zf));
            float og  = 1.f / (1.f + __expf(-zo));

            float m    = mval;
            float cnew = m * (c_reg * fg + cin * ig) + (1.f - m) * c_reg;
            c_reg = cnew;
            float ct = fminf(fmaxf(cnew, -30.f), 30.f);
            float e2 = __expf(-2.f * ct);
            y_out = m * (og * (1.f - e2) / (1.f + e2));
        }

        // ---- publish h(step+1): direct scattered STG (own cell), then flag
        if (step + 1 < T_STEPS)
            hT_out[(size_t)j_g * B_SZ + b_g] = y_out;
        __syncthreads();   // all hT STGs + all red reads complete
        if (step + 1 < T_STEPS && t == 0)
            st_release_exch(&g_flag[bid * 32], fbase + (unsigned)step + 1);

        // ---- deferred gmem writes (off the publish critical path)
        {
            size_t o = (size_t)step * (B_SZ * D_SZ) + (size_t)b_g * D_SZ + j_g;
            Y[o] = y_out;
            C[o] = c_reg;
            if (step == T_STEPS - 1) d_fin[(size_t)b_g * D_SZ + j_g] = c_reg;
        }

        // ---- prefetch next step's epilogue operands
        if (step + 1 < T_STEPS) {
            const float* itn = g_intern + (size_t)(step + 1) * (B_SZ * G4_SZ)
                             + (size_t)b_g * G4_SZ + j_g;
            in0 = __ldcg(itn);
            in1 = __ldcg(itn + 512);
            in2 = __ldcg(itn + 1024);
            in3 = __ldcg(itn + 1536);
            mval = __ldcg(iv + (size_t)(step + 1) * B_SZ + b_g);
        }
    }
}

// ---------------------------------------------------------------------------
// Launch. Inputs: X, Wf, Wr, bf, i, h0, c0. Output: Y[T,B,D]|C[T,B,D]|d[B,D]
// ---------------------------------------------------------------------------
extern "C" void kernel_launch(void* const* d_in, const int* in_sizes, int n_in,
                              void* d_out, int out_size)
{
    (void)in_sizes; (void)n_in; (void)out_size;
    const float* X  = (const float*)d_in[0];
    const float* Wf = (const float*)d_in[1];
    const float* Wr = (const float*)d_in[2];
    const float* bf = (const float*)d_in[3];
    const float* iv = (const float*)d_in[4];
    const float* h0 = (const float*)d_in[5];
    const float* c0 = (const float*)d_in[6];

    float* out  = (float*)d_out;
    float* Y    = out;
    float* C    = out + (size_t)T_STEPS * B_SZ * D_SZ;
    float* dfin = C   + (size_t)T_STEPS * B_SZ * D_SZ;

    float* hT0; cudaGetSymbolAddress((void**)&hT0, g_hT);

    h0_transpose_kernel<<<256, 256>>>(h0);

    dim3 g1(G4_SZ / 128, (T_STEPS * B_SZ) / 128);  // (16, 512)
    gemm_intern_kernel<<<g1, 256>>>(X, Wf, bf);

    cudaFuncSetAttribute(lstm_persistent_kernel,
                         cudaFuncAttributeMaxDynamicSharedMemorySize,
                         SMEM_F * (int)sizeof(float));
    lstm_persistent_kernel<<<128, THREADS, SMEM_F * sizeof(float)>>>(
        hT0, c0, iv, Wr, Y, C, dfin);
}